// round 2
// baseline (speedup 1.0000x reference)
#include <cuda_runtime.h>
#include <math.h>
#include <stdint.h>

#define NB 4
#define NT 8192
#define NC 64
#define NS 256
#define NV 256
#define NL 30
#define NTOK (NB*NT)
#define KC (2*NC)       /* 128 */
#define KSKIP (NL*NC)   /* 1920 */

// ---- device scratch (no allocations allowed) ----
__device__ float g_xa[NTOK*NC];
__device__ float g_xb[NTOK*NC];
__device__ float g_gates[(size_t)NTOK*KSKIP];   // [tok][l*64+c], ~252 MB
__device__ float g_skipb[NS];
__device__ float g_num;

// ---------------- prep: sum skip biases, zero loss accumulator --------------
__global__ void prep_kernel(const float* __restrict__ skip_b) {
    int s = threadIdx.x;
    float a = 0.f;
    #pragma unroll 6
    for (int l = 0; l < NL; l++) a += skip_b[l*NS + s];
    g_skipb[s] = a;
    if (s == 0) g_num = 0.f;
}

// ---------------- embedding of right-shifted labels --------------------------
__global__ void embed_kernel(const int* __restrict__ wf, const float* __restrict__ emb) {
    int tid = threadIdx.x;
    int tok = blockIdx.x*4 + (tid >> 6);
    int c   = tid & 63;
    int t   = tok & (NT-1);
    int lab = (t == 0) ? 128 : wf[tok-1];
    g_xa[tok*NC + c] = emb[lab*NC + c];
}

// ---------------- one WaveNet layer ------------------------------------------
// 64 tokens/CTA. warp owns 8 tokens, lane owns 4 conv-out cols (of 128).
__global__ __launch_bounds__(256, 1) void layer_kernel(
    const float* __restrict__ conv_w, const float* __restrict__ conv_b,
    const float* __restrict__ res_w,  const float* __restrict__ res_b,
    int l, int d, int flip)
{
    const float* __restrict__ xin  = flip ? g_xb : g_xa;
    float* __restrict__       xout = flip ? g_xa : g_xb;

    extern __shared__ float sm[];
    float* sW = sm;                 // [128][128] concat conv weights
    float* sX = sW + KC*KC;         // [128][64]  xcat transposed (k-major)
    float* sR = sX + KC*64;         // [64][64]   res weights
    float* sH = sR + NC*NC;         // [64][128]  pre-activation
    float* sG = sH + 64*KC;         // [64][64]   gate

    const int tid  = threadIdx.x;
    const int tok0 = blockIdx.x * 64;

    // stage weights: k<64 pairs with x[t] (conv_w[l,1]); k>=64 with x[t-d] (conv_w[l,0])
    for (int idx = tid; idx < KC*KC; idx += 256) {
        int k = idx >> 7, f = idx & 127;
        sW[idx] = (k < NC) ? conv_w[((l*2+1)*NC + k)*KC + f]
                           : conv_w[((l*2+0)*NC + (k-NC))*KC + f];
    }
    for (int idx = tid; idx < NC*NC; idx += 256)
        sR[idx] = res_w[l*NC*NC + idx];
    // gather-transposed activation tile: sX[k][j]
    for (int idx = tid; idx < KC*64; idx += 256) {
        int k = idx >> 6, j = idx & 63;
        int tok = tok0 + j;
        float v;
        if (k < NC) v = xin[tok*NC + k];
        else {
            int t = tok & (NT-1);
            v = (t >= d) ? xin[(tok-d)*NC + (k-NC)] : 0.f;
        }
        sX[idx] = v;
    }
    __syncthreads();

    const int warp = tid >> 5, lane = tid & 31;

    // conv GEMM: h = xcat @ Wcat + b   (M=64 tok, N=128, K=128)
    float acc[8][4];
    {
        float4 cb = *(const float4*)&conv_b[l*KC + lane*4];
        #pragma unroll
        for (int jj = 0; jj < 8; jj++) {
            acc[jj][0]=cb.x; acc[jj][1]=cb.y; acc[jj][2]=cb.z; acc[jj][3]=cb.w;
        }
    }
    #pragma unroll 4
    for (int k = 0; k < KC; k++) {
        float4 w  = *(const float4*)&sW[k*KC + lane*4];
        float4 a0 = *(const float4*)&sX[k*64 + warp*8];
        float4 a1 = *(const float4*)&sX[k*64 + warp*8 + 4];
        float a[8] = {a0.x,a0.y,a0.z,a0.w,a1.x,a1.y,a1.z,a1.w};
        #pragma unroll
        for (int jj = 0; jj < 8; jj++) {
            acc[jj][0] += a[jj]*w.x;
            acc[jj][1] += a[jj]*w.y;
            acc[jj][2] += a[jj]*w.z;
            acc[jj][3] += a[jj]*w.w;
        }
    }
    #pragma unroll
    for (int jj = 0; jj < 8; jj++) {
        float4 v = make_float4(acc[jj][0],acc[jj][1],acc[jj][2],acc[jj][3]);
        *(float4*)&sH[(warp*8+jj)*KC + lane*4] = v;
    }
    __syncthreads();

    // gate = tanh(h[:64]) * sigmoid(h[64:]); write to smem + global gates
    #pragma unroll
    for (int jj = 0; jj < 8; jj++) {
        int tk = warp*8 + jj;
        #pragma unroll
        for (int cc = 0; cc < 2; cc++) {
            int c = lane + 32*cc;
            float h1 = sH[tk*KC + c];
            float h2 = sH[tk*KC + NC + c];
            float g  = tanhf(h1) * (1.f / (1.f + expf(-h2)));
            sG[tk*NC + c] = g;
            g_gates[(size_t)(tok0+tk)*KSKIP + l*NC + c] = g;
        }
    }
    __syncthreads();

    // residual GEMM: xout = xin + gate @ res_w + res_b  (N=64, K=64)
    float acc2[8][2];
    {
        float r0 = res_b[l*NC + lane];
        float r1 = res_b[l*NC + lane + 32];
        #pragma unroll
        for (int jj = 0; jj < 8; jj++) { acc2[jj][0]=r0; acc2[jj][1]=r1; }
    }
    #pragma unroll 2
    for (int c4 = 0; c4 < 16; c4++) {
        float wA[4], wB[4];
        #pragma unroll
        for (int cc = 0; cc < 4; cc++) {
            wA[cc] = sR[(c4*4+cc)*NC + lane];
            wB[cc] = sR[(c4*4+cc)*NC + lane + 32];
        }
        #pragma unroll
        for (int jj = 0; jj < 8; jj++) {
            float4 gv = *(const float4*)&sG[(warp*8+jj)*NC + c4*4];
            acc2[jj][0] += gv.x*wA[0] + gv.y*wA[1] + gv.z*wA[2] + gv.w*wA[3];
            acc2[jj][1] += gv.x*wB[0] + gv.y*wB[1] + gv.z*wB[2] + gv.w*wB[3];
        }
    }
    #pragma unroll
    for (int jj = 0; jj < 8; jj++) {
        int tok = tok0 + warp*8 + jj;
        xout[tok*NC + lane]      = xin[tok*NC + lane]      + acc2[jj][0];
        xout[tok*NC + lane + 32] = xin[tok*NC + lane + 32] + acc2[jj][1];
    }
}

// ---------------- head helper: 64x256 <- 64x256 @ 256x256 (+bias, opt relu) --
__device__ __forceinline__ void gemm256(const float* sIn, const float* __restrict__ W,
                                        const float* __restrict__ bias, float* sOut,
                                        int warp, int lane, bool do_relu)
{
    float acc[8][8];
    {
        float4 bv0 = *(const float4*)&bias[lane*8];
        float4 bv1 = *(const float4*)&bias[lane*8 + 4];
        #pragma unroll
        for (int jj = 0; jj < 8; jj++) {
            acc[jj][0]=bv0.x; acc[jj][1]=bv0.y; acc[jj][2]=bv0.z; acc[jj][3]=bv0.w;
            acc[jj][4]=bv1.x; acc[jj][5]=bv1.y; acc[jj][6]=bv1.z; acc[jj][7]=bv1.w;
        }
    }
    for (int k = 0; k < 256; k += 4) {
        float a[8][4];
        #pragma unroll
        for (int jj = 0; jj < 8; jj++) {
            float4 v = *(const float4*)&sIn[(warp*8+jj)*256 + k];
            a[jj][0]=v.x; a[jj][1]=v.y; a[jj][2]=v.z; a[jj][3]=v.w;
        }
        #pragma unroll
        for (int cc = 0; cc < 4; cc++) {
            float4 u0 = *(const float4*)&W[(k+cc)*256 + lane*8];
            float4 u1 = *(const float4*)&W[(k+cc)*256 + lane*8 + 4];
            #pragma unroll
            for (int jj = 0; jj < 8; jj++) {
                acc[jj][0]+=a[jj][cc]*u0.x; acc[jj][1]+=a[jj][cc]*u0.y;
                acc[jj][2]+=a[jj][cc]*u0.z; acc[jj][3]+=a[jj][cc]*u0.w;
                acc[jj][4]+=a[jj][cc]*u1.x; acc[jj][5]+=a[jj][cc]*u1.y;
                acc[jj][6]+=a[jj][cc]*u1.z; acc[jj][7]+=a[jj][cc]*u1.w;
            }
        }
    }
    #pragma unroll
    for (int jj = 0; jj < 8; jj++) {
        float4 o0, o1;
        o0.x=acc[jj][0]; o0.y=acc[jj][1]; o0.z=acc[jj][2]; o0.w=acc[jj][3];
        o1.x=acc[jj][4]; o1.y=acc[jj][5]; o1.z=acc[jj][6]; o1.w=acc[jj][7];
        if (do_relu) {
            o0.x=fmaxf(o0.x,0.f); o0.y=fmaxf(o0.y,0.f); o0.z=fmaxf(o0.z,0.f); o0.w=fmaxf(o0.w,0.f);
            o1.x=fmaxf(o1.x,0.f); o1.y=fmaxf(o1.y,0.f); o1.z=fmaxf(o1.z,0.f); o1.w=fmaxf(o1.w,0.f);
        }
        *(float4*)&sOut[(warp*8+jj)*256 + lane*8]     = o0;
        *(float4*)&sOut[(warp*8+jj)*256 + lane*8 + 4] = o1;
    }
}

// ---------------- head: skip GEMM(K=1920) + w0/relu + w1 + CE ----------------
__global__ __launch_bounds__(256, 1) void head_kernel(
    const float* __restrict__ skip_w,
    const float* __restrict__ w0, const float* __restrict__ b0,
    const float* __restrict__ w1, const float* __restrict__ b1,
    const int* __restrict__ wf, const int* __restrict__ lens)
{
    extern __shared__ float sm[];
    float* sA   = sm;              // 64x256: skip_sum, then logits
    float* sHid = sm + 64*256;     // 64x256

    const int tid = threadIdx.x, warp = tid >> 5, lane = tid & 31;
    const int tok0 = blockIdx.x * 64;

    // phase 1: skip_sum = gates @ skip_w + sum(skip_b)    (K = 1920)
    float acc[8][8];
    {
        float4 bv0 = *(const float4*)&g_skipb[lane*8];
        float4 bv1 = *(const float4*)&g_skipb[lane*8 + 4];
        #pragma unroll
        for (int jj = 0; jj < 8; jj++) {
            acc[jj][0]=bv0.x; acc[jj][1]=bv0.y; acc[jj][2]=bv0.z; acc[jj][3]=bv0.w;
            acc[jj][4]=bv1.x; acc[jj][5]=bv1.y; acc[jj][6]=bv1.z; acc[jj][7]=bv1.w;
        }
    }
    for (int k = 0; k < KSKIP; k += 4) {
        float a[8][4];
        #pragma unroll
        for (int jj = 0; jj < 8; jj++) {
            float4 v = *(const float4*)(g_gates + (size_t)(tok0+warp*8+jj)*KSKIP + k);
            a[jj][0]=v.x; a[jj][1]=v.y; a[jj][2]=v.z; a[jj][3]=v.w;
        }
        #pragma unroll
        for (int cc = 0; cc < 4; cc++) {
            float4 u0 = *(const float4*)&skip_w[(k+cc)*NS + lane*8];
            float4 u1 = *(const float4*)&skip_w[(k+cc)*NS + lane*8 + 4];
            #pragma unroll
            for (int jj = 0; jj < 8; jj++) {
                acc[jj][0]+=a[jj][cc]*u0.x; acc[jj][1]+=a[jj][cc]*u0.y;
                acc[jj][2]+=a[jj][cc]*u0.z; acc[jj][3]+=a[jj][cc]*u0.w;
                acc[jj][4]+=a[jj][cc]*u1.x; acc[jj][5]+=a[jj][cc]*u1.y;
                acc[jj][6]+=a[jj][cc]*u1.z; acc[jj][7]+=a[jj][cc]*u1.w;
            }
        }
    }
    #pragma unroll
    for (int jj = 0; jj < 8; jj++) {
        *(float4*)&sA[(warp*8+jj)*256 + lane*8]     = make_float4(acc[jj][0],acc[jj][1],acc[jj][2],acc[jj][3]);
        *(float4*)&sA[(warp*8+jj)*256 + lane*8 + 4] = make_float4(acc[jj][4],acc[jj][5],acc[jj][6],acc[jj][7]);
    }
    __syncthreads();

    // phase 2: hid0 = relu(skip @ w0 + b0)
    gemm256(sA, w0, b0, sHid, warp, lane, true);
    __syncthreads();
    // phase 3: logits = hid0 @ w1 + b1  (into sA)
    gemm256(sHid, w1, b1, sA, warp, lane, false);
    __syncthreads();

    // phase 4: masked CE, warp-cooperative per token
    float local = 0.f;
    for (int jj = 0; jj < 8; jj++) {
        int tkl = warp*8 + jj;
        int tok = tok0 + tkl;
        float v[8];
        #pragma unroll
        for (int i = 0; i < 8; i++) v[i] = sA[tkl*256 + lane*8 + i];
        float m = v[0];
        #pragma unroll
        for (int i = 1; i < 8; i++) m = fmaxf(m, v[i]);
        #pragma unroll
        for (int off = 16; off; off >>= 1) m = fmaxf(m, __shfl_xor_sync(0xffffffffu, m, off));
        float s = 0.f;
        #pragma unroll
        for (int i = 0; i < 8; i++) s += expf(v[i] - m);
        #pragma unroll
        for (int off = 16; off; off >>= 1) s += __shfl_xor_sync(0xffffffffu, s, off);
        if (lane == 0) {
            int t = tok & (NT-1);
            int b = tok >> 13;
            if (t < lens[b]) {
                int lab = wf[tok];
                local += m + logf(s) - sA[tkl*256 + lab];
            }
        }
    }
    if (lane == 0) atomicAdd(&g_num, local);
}

__global__ void finalize_kernel(const int* __restrict__ lens, float* __restrict__ out) {
    float denom = 0.f;
    for (int b = 0; b < NB; b++) denom += (float)lens[b];
    out[0] = g_num / fmaxf(denom, 1.f);
}

// ---------------- launcher ---------------------------------------------------
extern "C" void kernel_launch(void* const* d_in, const int* in_sizes, int n_in,
                              void* d_out, int out_size)
{
    const int*   wf     = (const int*)d_in[0];
    const int*   lens   = (const int*)d_in[1];
    const float* emb    = (const float*)d_in[2];
    const float* conv_w = (const float*)d_in[3];
    const float* conv_b = (const float*)d_in[4];
    const float* res_w  = (const float*)d_in[5];
    const float* res_b  = (const float*)d_in[6];
    const float* skip_w = (const float*)d_in[7];
    const float* skip_b = (const float*)d_in[8];
    const float* w0     = (const float*)d_in[9];
    const float* b0     = (const float*)d_in[10];
    const float* w1     = (const float*)d_in[11];
    const float* b1     = (const float*)d_in[12];

    static const int dil[NL] = {1,2,4,8,16,32,64,128,256,512,
                                1,2,4,8,16,32,64,128,256,512,
                                1,2,4,8,16,32,64,128,256,512};

    const int LAYER_SMEM = (KC*KC + KC*64 + NC*NC + 64*KC + 64*NC) * (int)sizeof(float); // 160 KB
    const int HEAD_SMEM  = 2*64*256 * (int)sizeof(float);                                 // 128 KB
    cudaFuncSetAttribute(layer_kernel, cudaFuncAttributeMaxDynamicSharedMemorySize, LAYER_SMEM);
    cudaFuncSetAttribute(head_kernel,  cudaFuncAttributeMaxDynamicSharedMemorySize, HEAD_SMEM);

    prep_kernel<<<1, NS>>>(skip_b);
    embed_kernel<<<NTOK/4, 256>>>(wf, emb);
    for (int i = 0; i < NL; i++)
        layer_kernel<<<NTOK/64, 256, LAYER_SMEM>>>(conv_w, conv_b, res_w, res_b,
                                                   i, dil[i], i & 1);
    head_kernel<<<NTOK/64, 256, HEAD_SMEM>>>(skip_w, w0, b0, w1, b1, wf, lens);
    finalize_kernel<<<1, 1>>>(lens, (float*)d_out);
}

// round 4
// speedup vs baseline: 5.6199x; 5.6199x over previous
#include <cuda_runtime.h>
#include <cuda_bf16.h>
#include <math.h>
#include <stdint.h>

#define NB 4
#define NT 8192
#define NC 64
#define NS 256
#define NV 256
#define NL 30
#define NTOK (NB*NT)

// ---------------- device scratch ---------------------------------------------
__device__ float g_xa[NTOK*NC];
__device__ float g_xb[NTOK*NC];
__device__ __nv_bfloat16 g_gates[(size_t)NL*NTOK*NC];   // [l][tok][64]
__device__ __nv_bfloat16 g_convw[NL*128*128];           // [l][f][k]
__device__ __nv_bfloat16 g_resw[NL*64*64];              // [l][o][k]
__device__ __nv_bfloat16 g_skipw[NL*256*64];            // [l][v][k]
__device__ __nv_bfloat16 g_w0t[256*256];                // [v][k]
__device__ __nv_bfloat16 g_w1t[256*256];                // [v][k]
__device__ float g_skipb[NS];
__device__ float g_num;

__device__ __forceinline__ void mma16816(float* c, uint32_t a0, uint32_t a1,
                                         uint32_t a2, uint32_t a3,
                                         uint32_t b0, uint32_t b1){
  asm volatile("mma.sync.aligned.m16n8k16.row.col.f32.bf16.bf16.f32 "
    "{%0,%1,%2,%3}, {%4,%5,%6,%7}, {%8,%9}, {%0,%1,%2,%3};"
    : "+f"(c[0]), "+f"(c[1]), "+f"(c[2]), "+f"(c[3])
    : "r"(a0), "r"(a1), "r"(a2), "r"(a3), "r"(b0), "r"(b1));
}
__device__ __forceinline__ uint32_t pack2(float a, float b){
  __nv_bfloat162 t = __floats2bfloat162_rn(a, b);
  return *(uint32_t*)&t;
}

// ---------------- prep: weight transposes to bf16 -----------------------------
__global__ void prep_w_kernel(const float* __restrict__ conv_w,
                              const float* __restrict__ res_w,
                              const float* __restrict__ skip_w,
                              const float* __restrict__ w0,
                              const float* __restrict__ w1){
  int idx = blockIdx.x*256 + threadIdx.x;
  if (idx < NL*128*128){
    int k = idx & 127, f = (idx>>7)&127, l = idx>>14;
    float v = (k < 64) ? conv_w[((l*2+1)*64 + k)*128 + f]
                       : conv_w[((l*2+0)*64 + (k-64))*128 + f];
    g_convw[((size_t)l*128 + f)*128 + k] = __float2bfloat16(v);
    return;
  }
  idx -= NL*128*128;
  if (idx < NL*64*64){
    int k = idx & 63, o = (idx>>6)&63, l = idx>>12;
    g_resw[((size_t)l*64 + o)*64 + k] = __float2bfloat16(res_w[((size_t)l*64 + k)*64 + o]);
    return;
  }
  idx -= NL*64*64;
  if (idx < NL*256*64){
    int k = idx & 63, v2 = (idx>>6)&255, l = idx>>14;
    g_skipw[((size_t)l*256 + v2)*64 + k] = __float2bfloat16(skip_w[((size_t)l*64 + k)*256 + v2]);
    return;
  }
  idx -= NL*256*64;
  if (idx < 256*256){
    int k = idx & 255, v2 = idx>>8;
    g_w0t[v2*256 + k] = __float2bfloat16(w0[k*256 + v2]);
    return;
  }
  idx -= 256*256;
  if (idx < 256*256){
    int k = idx & 255, v2 = idx>>8;
    g_w1t[v2*256 + k] = __float2bfloat16(w1[k*256 + v2]);
  }
}

__global__ void prep_misc_kernel(const float* __restrict__ skip_b){
  int s = threadIdx.x;
  float a = 0.f;
  #pragma unroll 6
  for (int l = 0; l < NL; l++) a += skip_b[l*NS + s];
  g_skipb[s] = a;
  if (s == 0) g_num = 0.f;
}

__global__ void embed_kernel(const int* __restrict__ wf, const float* __restrict__ emb){
  int tid = threadIdx.x;
  int tok = blockIdx.x*4 + (tid >> 6);
  int c   = tid & 63;
  int t   = tok & (NT-1);
  int lab = (t == 0) ? 128 : wf[tok-1];
  g_xa[(size_t)tok*NC + c] = emb[lab*NC + c];
}

// ---------------- layer kernel (warp HMMA) ------------------------------------
// smem: sCB@0(512) sRB@512(256) sA@768 (128x272B) sW@35584 (128x272B) sR@70400 (64x144B)
#define LOFF_CB 0
#define LOFF_RB 512
#define LOFF_A  768
#define LOFF_W  35584
#define LOFF_R  70400
#define LSMEM   79616
#define APITCH  272
#define RPITCH  144

__global__ __launch_bounds__(256) void layer_kernel(
    const float* __restrict__ conv_b, const float* __restrict__ res_b,
    int l, int d, int flip)
{
  extern __shared__ char sm[];
  const float* __restrict__ xin  = flip ? g_xb : g_xa;
  float* __restrict__       xout = flip ? g_xa : g_xb;

  const int tid = threadIdx.x, warp = tid >> 5, lane = tid & 31;
  const int l4 = lane >> 2, q = lane & 3;
  const int tok0 = blockIdx.x * 128;

  float* sCB = (float*)(sm + LOFF_CB);
  float* sRB = (float*)(sm + LOFF_RB);

  if (tid < 128) sCB[tid] = conv_b[l*128 + tid];
  if (tid < 64)  sRB[tid] = res_b[l*64 + tid];

  { // stage A-cat [tok][128] bf16 (k<64: x[t], k>=64: x[t-d])
    int tk = tid >> 1, h = tid & 1;
    int tok = tok0 + tk;
    char* dst = sm + LOFF_A + tk*APITCH + h*128;
    int t = tok & (NT-1);
    const float* src = (h == 0) ? (xin + (size_t)tok*64)
                     : ((t >= d) ? (xin + (size_t)(tok-d)*64) : nullptr);
    if (src){
      #pragma unroll
      for (int i = 0; i < 8; i++){
        float4 v0 = *(const float4*)(src + i*8);
        float4 v1 = *(const float4*)(src + i*8 + 4);
        *(uint4*)(dst + i*16) = make_uint4(pack2(v0.x,v0.y), pack2(v0.z,v0.w),
                                           pack2(v1.x,v1.y), pack2(v1.z,v1.w));
      }
    } else {
      uint4 z = make_uint4(0,0,0,0);
      #pragma unroll
      for (int i = 0; i < 8; i++) *(uint4*)(dst + i*16) = z;
    }
  }
  { // stage conv W^T [f][128]
    int f = tid >> 1, h = tid & 1;
    const uint4* src = (const uint4*)(g_convw + (size_t)l*16384 + f*128 + h*64);
    char* dst = sm + LOFF_W + f*APITCH + h*128;
    #pragma unroll
    for (int i = 0; i < 8; i++) *(uint4*)(dst + i*16) = src[i];
  }
  if (tid < 64){ // stage resw^T [o][64]
    const uint4* src = (const uint4*)(g_resw + (size_t)l*4096 + tid*64);
    char* dst = sm + LOFF_R + tid*RPITCH;
    #pragma unroll
    for (int i = 0; i < 8; i++) *(uint4*)(dst + i*16) = src[i];
  }
  __syncthreads();

  // conv GEMM: 16 tok x 128 N per warp, K=128
  float acc[16][4];
  #pragma unroll
  for (int j = 0; j < 16; j++){ acc[j][0]=0; acc[j][1]=0; acc[j][2]=0; acc[j][3]=0; }

  const char* aBase = sm + LOFF_A + (warp*16 + l4)*APITCH + q*4;
  const char* wBase = sm + LOFF_W + l4*APITCH + q*4;
  #pragma unroll
  for (int s = 0; s < 8; s++){
    uint32_t a0 = *(const uint32_t*)(aBase + s*32);
    uint32_t a1 = *(const uint32_t*)(aBase + s*32 + 8*APITCH);
    uint32_t a2 = *(const uint32_t*)(aBase + s*32 + 16);
    uint32_t a3 = *(const uint32_t*)(aBase + s*32 + 8*APITCH + 16);
    #pragma unroll
    for (int j = 0; j < 16; j++){
      uint32_t b0 = *(const uint32_t*)(wBase + j*8*APITCH + s*32);
      uint32_t b1 = *(const uint32_t*)(wBase + j*8*APITCH + s*32 + 16);
      mma16816(acc[j], a0, a1, a2, a3, b0, b1);
    }
  }

  // gate (register-resident): G[j][r] = bf16x2 at (row r, cols j*8+q*2, +1)
  uint32_t G[8][2];
  #pragma unroll
  for (int j = 0; j < 8; j++){
    int c0 = j*8 + q*2;
    float b1c = sCB[c0], b2c = sCB[c0+1], b1s = sCB[64+c0], b2s = sCB[64+c0+1];
    #pragma unroll
    for (int r = 0; r < 2; r++){
      float h1a = acc[j][2*r]     + b1c;
      float h1b = acc[j][2*r+1]   + b2c;
      float h2a = acc[j+8][2*r]   + b1s;
      float h2b = acc[j+8][2*r+1] + b2s;
      float ga = (__fdividef(2.f, 1.f + __expf(-2.f*h1a)) - 1.f)
               *  __fdividef(1.f, 1.f + __expf(-h2a));
      float gb = (__fdividef(2.f, 1.f + __expf(-2.f*h1b)) - 1.f)
               *  __fdividef(1.f, 1.f + __expf(-h2b));
      G[j][r] = pack2(ga, gb);
    }
  }

  // gates -> global [l][tok][64]
  {
    __nv_bfloat16* gp = g_gates + ((size_t)l*NTOK + tok0 + warp*16)*64;
    #pragma unroll
    for (int j = 0; j < 8; j++){
      *(uint32_t*)(gp + (size_t)l4*64      + j*8 + q*2) = G[j][0];
      *(uint32_t*)(gp + (size_t)(l4+8)*64  + j*8 + q*2) = G[j][1];
    }
  }

  // residual GEMM: 16 tok x 64 N, K=64, A-frags directly from G regs
  float r2[8][4];
  #pragma unroll
  for (int j = 0; j < 8; j++){ r2[j][0]=0; r2[j][1]=0; r2[j][2]=0; r2[j][3]=0; }
  const char* rBase = sm + LOFF_R + l4*RPITCH + q*4;
  #pragma unroll
  for (int s = 0; s < 4; s++){
    uint32_t a0 = G[2*s][0], a1 = G[2*s][1], a2 = G[2*s+1][0], a3 = G[2*s+1][1];
    #pragma unroll
    for (int j = 0; j < 8; j++){
      uint32_t b0 = *(const uint32_t*)(rBase + j*8*RPITCH + s*32);
      uint32_t b1 = *(const uint32_t*)(rBase + j*8*RPITCH + s*32 + 16);
      mma16816(r2[j], a0, a1, a2, a3, b0, b1);
    }
  }

  // writeback: xout = xin + res + rb
  {
    int tokA = tok0 + warp*16 + l4;
    int tokB = tokA + 8;
    #pragma unroll
    for (int j = 0; j < 8; j++){
      int c0 = j*8 + q*2;
      float rb0 = sRB[c0], rb1 = sRB[c0+1];
      float2 xa = *(const float2*)(xin + (size_t)tokA*64 + c0);
      float2 xb = *(const float2*)(xin + (size_t)tokB*64 + c0);
      *(float2*)(xout + (size_t)tokA*64 + c0) = make_float2(xa.x + r2[j][0] + rb0,
                                                            xa.y + r2[j][1] + rb1);
      *(float2*)(xout + (size_t)tokB*64 + c0) = make_float2(xb.x + r2[j][2] + rb0,
                                                            xb.y + r2[j][3] + rb1);
    }
  }
}

// ---------------- head kernel --------------------------------------------------
// smem: skb@0 b0@1024 b1@2048; phase1: sG@3072(128x144) sWc@21504(256x144)
//       phase2/3: sW2@3072(256x272).  HSMEM = 72704
#define HOFF_SKB 0
#define HOFF_B0  1024
#define HOFF_B1  2048
#define HOFF_G   3072
#define HOFF_WC  21504
#define HOFF_W2  3072
#define HSMEM    72704
#define WPITCH2  272

__global__ __launch_bounds__(256) void head_kernel(
    const float* __restrict__ b0, const float* __restrict__ b1,
    const int* __restrict__ wf, const int* __restrict__ lens)
{
  extern __shared__ char sm[];
  const int tid = threadIdx.x, warp = tid >> 5, lane = tid & 31;
  const int l4 = lane >> 2, q = lane & 3;
  const int tok0 = blockIdx.x * 128;

  float* sSKB = (float*)(sm + HOFF_SKB);
  float* sB0  = (float*)(sm + HOFF_B0);
  float* sB1  = (float*)(sm + HOFF_B1);
  if (tid < 256){
    sSKB[tid] = g_skipb[tid];
    sB0[tid]  = b0[tid];
    sB1[tid]  = b1[tid];
  }

  // ---- phase 1: skip_sum = sum_l gates_l @ skipw_l^T  (K=1920) ----
  float acc[32][4];
  #pragma unroll
  for (int j = 0; j < 32; j++){ acc[j][0]=0; acc[j][1]=0; acc[j][2]=0; acc[j][3]=0; }

  for (int l = 0; l < NL; l++){
    __syncthreads();
    { // gates chunk [128][64] -> sG [128][72]
      int r = tid >> 1, h = tid & 1;
      const uint4* src = (const uint4*)(g_gates + ((size_t)l*NTOK + tok0 + r)*64 + h*32);
      uint4* dst = (uint4*)(sm + HOFF_G + r*RPITCH + h*64);
      dst[0]=src[0]; dst[1]=src[1]; dst[2]=src[2]; dst[3]=src[3];
    }
    { // skipw chunk [256][64] -> sWc [256][72]
      const uint4* src = (const uint4*)(g_skipw + ((size_t)l*256 + tid)*64);
      uint4* dst = (uint4*)(sm + HOFF_WC + tid*RPITCH);
      #pragma unroll
      for (int i = 0; i < 8; i++) dst[i] = src[i];
    }
    __syncthreads();

    const char* aBase = sm + HOFF_G  + (warp*16 + l4)*RPITCH + q*4;
    const char* wBase = sm + HOFF_WC + l4*RPITCH + q*4;
    #pragma unroll
    for (int s = 0; s < 4; s++){
      uint32_t a0 = *(const uint32_t*)(aBase + s*32);
      uint32_t a1 = *(const uint32_t*)(aBase + s*32 + 8*RPITCH);
      uint32_t a2 = *(const uint32_t*)(aBase + s*32 + 16);
      uint32_t a3 = *(const uint32_t*)(aBase + s*32 + 8*RPITCH + 16);
      #pragma unroll
      for (int j = 0; j < 32; j++){
        uint32_t b0r = *(const uint32_t*)(wBase + j*8*RPITCH + s*32);
        uint32_t b1r = *(const uint32_t*)(wBase + j*8*RPITCH + s*32 + 16);
        mma16816(acc[j], a0, a1, a2, a3, b0r, b1r);
      }
    }
  }

  // pack P = bf16(acc + skipb)
  uint32_t P[32][2];
  #pragma unroll
  for (int j = 0; j < 32; j++){
    int c0 = j*8 + q*2;
    float s0 = sSKB[c0], s1 = sSKB[c0+1];
    P[j][0] = pack2(acc[j][0] + s0, acc[j][1] + s1);
    P[j][1] = pack2(acc[j][2] + s0, acc[j][3] + s1);
  }

  // ---- phase 2: hid = relu(s @ w0^T + b0), K=256 over 2 chunks ----
  #pragma unroll
  for (int j = 0; j < 32; j++){ acc[j][0]=0; acc[j][1]=0; acc[j][2]=0; acc[j][3]=0; }
  for (int kc = 0; kc < 2; kc++){
    __syncthreads();
    { // w0t chunk [256][128] -> sW2 [256][136]
      const uint4* src = (const uint4*)(g_w0t + tid*256 + kc*128);
      uint4* dst = (uint4*)(sm + HOFF_W2 + tid*WPITCH2);
      #pragma unroll
      for (int i = 0; i < 16; i++) dst[i] = src[i];
    }
    __syncthreads();
    const char* wBase = sm + HOFF_W2 + l4*WPITCH2 + q*4;
    #pragma unroll
    for (int s = 0; s < 8; s++){
      int S = kc*8 + s;
      uint32_t a0 = P[2*S][0], a1 = P[2*S][1], a2 = P[2*S+1][0], a3 = P[2*S+1][1];
      #pragma unroll
      for (int j = 0; j < 32; j++){
        uint32_t b0r = *(const uint32_t*)(wBase + j*8*WPITCH2 + s*32);
        uint32_t b1r = *(const uint32_t*)(wBase + j*8*WPITCH2 + s*32 + 16);
        mma16816(acc[j], a0, a1, a2, a3, b0r, b1r);
      }
    }
  }
  #pragma unroll
  for (int j = 0; j < 32; j++){
    int c0 = j*8 + q*2;
    float s0 = sB0[c0], s1 = sB0[c0+1];
    P[j][0] = pack2(fmaxf(acc[j][0] + s0, 0.f), fmaxf(acc[j][1] + s1, 0.f));
    P[j][1] = pack2(fmaxf(acc[j][2] + s0, 0.f), fmaxf(acc[j][3] + s1, 0.f));
  }

  // ---- phase 3: logits = hid @ w1^T, K=256 ----
  #pragma unroll
  for (int j = 0; j < 32; j++){ acc[j][0]=0; acc[j][1]=0; acc[j][2]=0; acc[j][3]=0; }
  for (int kc = 0; kc < 2; kc++){
    __syncthreads();
    {
      const uint4* src = (const uint4*)(g_w1t + tid*256 + kc*128);
      uint4* dst = (uint4*)(sm + HOFF_W2 + tid*WPITCH2);
      #pragma unroll
      for (int i = 0; i < 16; i++) dst[i] = src[i];
    }
    __syncthreads();
    const char* wBase = sm + HOFF_W2 + l4*WPITCH2 + q*4;
    #pragma unroll
    for (int s = 0; s < 8; s++){
      int S = kc*8 + s;
      uint32_t a0 = P[2*S][0], a1 = P[2*S][1], a2 = P[2*S+1][0], a3 = P[2*S+1][1];
      #pragma unroll
      for (int j = 0; j < 32; j++){
        uint32_t b0r = *(const uint32_t*)(wBase + j*8*WPITCH2 + s*32);
        uint32_t b1r = *(const uint32_t*)(wBase + j*8*WPITCH2 + s*32 + 16);
        mma16816(acc[j], a0, a1, a2, a3, b0r, b1r);
      }
    }
  }

  // ---- CE: per-token log-softmax over 256 logits ----
  float local = 0.f;
  int tokA = tok0 + warp*16 + l4;
  #pragma unroll
  for (int r = 0; r < 2; r++){
    int tok = tokA + r*8;
    int lab = wf[tok];
    float m = -1e30f;
    #pragma unroll
    for (int j = 0; j < 32; j++){
      int c0 = j*8 + q*2;
      float v0 = acc[j][2*r]   + sB1[c0];
      float v1 = acc[j][2*r+1] + sB1[c0+1];
      m = fmaxf(m, fmaxf(v0, v1));
    }
    m = fmaxf(m, __shfl_xor_sync(0xffffffffu, m, 1));
    m = fmaxf(m, __shfl_xor_sync(0xffffffffu, m, 2));
    float s = 0.f, lv = 0.f;
    #pragma unroll
    for (int j = 0; j < 32; j++){
      int c0 = j*8 + q*2;
      float v0 = acc[j][2*r]   + sB1[c0];
      float v1 = acc[j][2*r+1] + sB1[c0+1];
      s += __expf(v0 - m) + __expf(v1 - m);
      if (lab == c0)   lv += v0;
      if (lab == c0+1) lv += v1;
    }
    s  += __shfl_xor_sync(0xffffffffu, s, 1);
    s  += __shfl_xor_sync(0xffffffffu, s, 2);
    lv += __shfl_xor_sync(0xffffffffu, lv, 1);
    lv += __shfl_xor_sync(0xffffffffu, lv, 2);
    float ce = m + logf(s) - lv;
    int t = tok & (NT-1);
    int b = tok >> 13;
    if (q == 0 && t < lens[b]) local += ce;
  }
  #pragma unroll
  for (int off = 16; off; off >>= 1)
    local += __shfl_xor_sync(0xffffffffu, local, off);
  if (lane == 0) atomicAdd(&g_num, local);
}

__global__ void finalize_kernel(const int* __restrict__ lens, float* __restrict__ out){
  float denom = 0.f;
  for (int b = 0; b < NB; b++) denom += (float)lens[b];
  out[0] = g_num / fmaxf(denom, 1.f);
}

// ---------------- launcher -----------------------------------------------------
extern "C" void kernel_launch(void* const* d_in, const int* in_sizes, int n_in,
                              void* d_out, int out_size)
{
  const int*   wf     = (const int*)d_in[0];
  const int*   lens   = (const int*)d_in[1];
  const float* emb    = (const float*)d_in[2];
  const float* conv_w = (const float*)d_in[3];
  const float* conv_b = (const float*)d_in[4];
  const float* res_w  = (const float*)d_in[5];
  const float* res_b  = (const float*)d_in[6];
  const float* skip_w = (const float*)d_in[7];
  const float* skip_b = (const float*)d_in[8];
  const float* w0     = (const float*)d_in[9];
  const float* b0     = (const float*)d_in[10];
  const float* w1     = (const float*)d_in[11];
  const float* b1     = (const float*)d_in[12];

  static const int dil[NL] = {1,2,4,8,16,32,64,128,256,512,
                              1,2,4,8,16,32,64,128,256,512,
                              1,2,4,8,16,32,64,128,256,512};

  cudaFuncSetAttribute(layer_kernel, cudaFuncAttributeMaxDynamicSharedMemorySize, LSMEM);
  cudaFuncSetAttribute(head_kernel,  cudaFuncAttributeMaxDynamicSharedMemorySize, HSMEM);

  prep_misc_kernel<<<1, NS>>>(skip_b);
  prep_w_kernel<<<4832, 256>>>(conv_w, res_w, skip_w, w0, w1);
  embed_kernel<<<NTOK/4, 256>>>(wf, emb);
  for (int i = 0; i < NL; i++)
    layer_kernel<<<NTOK/128, 256, LSMEM>>>(conv_b, res_b, i, dil[i], i & 1);
  head_kernel<<<NTOK/128, 256, HSMEM>>>(b0, b1, wf, lens);
  finalize_kernel<<<1, 1>>>(lens, (float*)d_out);
}

// round 5
// speedup vs baseline: 7.5379x; 1.3413x over previous
#include <cuda_runtime.h>
#include <cuda_bf16.h>
#include <math.h>
#include <stdint.h>

#define NB 4
#define NT 8192
#define NC 64
#define NS 256
#define NV 256
#define NL 30
#define NTOK (NB*NT)

// ---------------- device scratch ---------------------------------------------
__device__ float g_xa[NTOK*NC];
__device__ float g_xb[NTOK*NC];
__device__ __nv_bfloat16 g_gates[(size_t)NL*NTOK*NC];   // [l][tok][64]
__device__ __nv_bfloat16 g_convw[NL*128*128];           // [l][f][k]
__device__ __nv_bfloat16 g_resw[NL*64*64];              // [l][o][k]
__device__ __nv_bfloat16 g_skipw[NL*256*64];            // [l][v][k]
__device__ __nv_bfloat16 g_w0t[256*256];                // [v][k]
__device__ __nv_bfloat16 g_w1t[256*256];                // [v][k]
__device__ float g_skipb[NS];
__device__ float g_num;

// ---------------- helpers ------------------------------------------------------
__device__ __forceinline__ uint32_t s2u(const void* p){
  uint32_t a;
  asm("{ .reg .u64 t; cvta.to.shared.u64 t, %1; cvt.u32.u64 %0, t; }" : "=r"(a) : "l"(p));
  return a;
}
__device__ __forceinline__ void mma16816(float* c, uint32_t a0, uint32_t a1,
                                         uint32_t a2, uint32_t a3,
                                         uint32_t b0, uint32_t b1){
  asm volatile("mma.sync.aligned.m16n8k16.row.col.f32.bf16.bf16.f32 "
    "{%0,%1,%2,%3}, {%4,%5,%6,%7}, {%8,%9}, {%0,%1,%2,%3};"
    : "+f"(c[0]), "+f"(c[1]), "+f"(c[2]), "+f"(c[3])
    : "r"(a0), "r"(a1), "r"(a2), "r"(a3), "r"(b0), "r"(b1));
}
__device__ __forceinline__ void ldsm4(uint32_t* r, uint32_t a){
  asm volatile("ldmatrix.sync.aligned.m8n8.x4.shared.b16 {%0,%1,%2,%3}, [%4];"
    : "=r"(r[0]), "=r"(r[1]), "=r"(r[2]), "=r"(r[3]) : "r"(a));
}
__device__ __forceinline__ void cp16(uint32_t d, const void* s){
  asm volatile("cp.async.ca.shared.global [%0], [%1], 16;" :: "r"(d), "l"(s));
}
#define CP_COMMIT() asm volatile("cp.async.commit_group;" ::: "memory")
#define CP_WAIT0()  asm volatile("cp.async.wait_group 0;" ::: "memory")
#define CP_WAIT1()  asm volatile("cp.async.wait_group 1;" ::: "memory")

__device__ __forceinline__ uint32_t pack2(float a, float b){
  __nv_bfloat162 t = __floats2bfloat162_rn(a, b);
  return *(uint32_t*)&t;
}

// ---------------- prep ----------------------------------------------------------
__global__ void prep_w_kernel(const float* __restrict__ conv_w,
                              const float* __restrict__ res_w,
                              const float* __restrict__ skip_w,
                              const float* __restrict__ w0,
                              const float* __restrict__ w1){
  int idx = blockIdx.x*256 + threadIdx.x;
  if (idx < NL*128*128){
    int k = idx & 127, f = (idx>>7)&127, l = idx>>14;
    float v = (k < 64) ? conv_w[((l*2+1)*64 + k)*128 + f]
                       : conv_w[((l*2+0)*64 + (k-64))*128 + f];
    g_convw[((size_t)l*128 + f)*128 + k] = __float2bfloat16(v);
    return;
  }
  idx -= NL*128*128;
  if (idx < NL*64*64){
    int k = idx & 63, o = (idx>>6)&63, l = idx>>12;
    g_resw[((size_t)l*64 + o)*64 + k] = __float2bfloat16(res_w[((size_t)l*64 + k)*64 + o]);
    return;
  }
  idx -= NL*64*64;
  if (idx < NL*256*64){
    int k = idx & 63, v2 = (idx>>6)&255, l = idx>>14;
    g_skipw[((size_t)l*256 + v2)*64 + k] = __float2bfloat16(skip_w[((size_t)l*64 + k)*256 + v2]);
    return;
  }
  idx -= NL*256*64;
  if (idx < 256*256){
    int k = idx & 255, v2 = idx>>8;
    g_w0t[v2*256 + k] = __float2bfloat16(w0[k*256 + v2]);
    return;
  }
  idx -= 256*256;
  if (idx < 256*256){
    int k = idx & 255, v2 = idx>>8;
    g_w1t[v2*256 + k] = __float2bfloat16(w1[k*256 + v2]);
  }
}

__global__ void prep_misc_kernel(const float* __restrict__ skip_b){
  int s = threadIdx.x;
  float a = 0.f;
  #pragma unroll 6
  for (int l = 0; l < NL; l++) a += skip_b[l*NS + s];
  g_skipb[s] = a;
  if (s == 0) g_num = 0.f;
}

__global__ void embed_kernel(const int* __restrict__ wf, const float* __restrict__ emb){
  int tid = threadIdx.x;
  int tok = blockIdx.x*4 + (tid >> 6);
  int c   = tid & 63;
  int t   = tok & (NT-1);
  int lab = (t == 0) ? 128 : wf[tok-1];
  g_xa[(size_t)tok*NC + c] = emb[lab*NC + c];
}

// ---------------- layer kernel ---------------------------------------------------
#define LOFF_CB 0
#define LOFF_RB 512
#define LOFF_A  768
#define LOFF_W  35584
#define LOFF_R  70400
#define LOFF_G  79616
#define LSMEM   98048
#define APITCH  272
#define RPITCH  144

__global__ __launch_bounds__(256, 2) void layer_kernel(
    const float* __restrict__ conv_b, const float* __restrict__ res_b,
    int l, int d, int flip)
{
  extern __shared__ char sm[];
  uint32_t sbase = s2u(sm);
  const float* __restrict__ xin  = flip ? g_xb : g_xa;
  float* __restrict__       xout = flip ? g_xa : g_xb;

  const int tid = threadIdx.x, warp = tid >> 5, lane = tid & 31;
  const int l4 = lane >> 2, q = lane & 3;
  const int tok0 = blockIdx.x * 128;

  // async weight staging
  {
    const char* wsrc = (const char*)(g_convw + (size_t)l*16384);
    #pragma unroll
    for (int i = 0; i < 8; i++){
      int idx = tid + i*256, row = idx >> 4, c = idx & 15;
      cp16(sbase + LOFF_W + row*APITCH + c*16, wsrc + row*256 + c*16);
    }
    const char* rsrc = (const char*)(g_resw + (size_t)l*4096);
    #pragma unroll
    for (int i = 0; i < 2; i++){
      int idx = tid + i*256, row = idx >> 3, c = idx & 7;
      cp16(sbase + LOFF_R + row*RPITCH + c*16, rsrc + row*128 + c*16);
    }
    CP_COMMIT();
  }

  float* sCB = (float*)(sm + LOFF_CB);
  float* sRB = (float*)(sm + LOFF_RB);
  if (tid < 128) sCB[tid] = conv_b[l*128 + tid];
  if (tid < 64)  sRB[tid] = res_b[l*64 + tid];

  { // stage A-cat [tok][128] bf16 (k<64: x[t], k>=64: x[t-d])
    int tk = tid >> 1, h = tid & 1;
    int tok = tok0 + tk;
    char* dst = sm + LOFF_A + tk*APITCH + h*128;
    int t = tok & (NT-1);
    const float* src = (h == 0) ? (xin + (size_t)tok*64)
                     : ((t >= d) ? (xin + (size_t)(tok-d)*64) : nullptr);
    if (src){
      #pragma unroll
      for (int i = 0; i < 8; i++){
        float4 v0 = *(const float4*)(src + i*8);
        float4 v1 = *(const float4*)(src + i*8 + 4);
        *(uint4*)(dst + i*16) = make_uint4(pack2(v0.x,v0.y), pack2(v0.z,v0.w),
                                           pack2(v1.x,v1.y), pack2(v1.z,v1.w));
      }
    } else {
      uint4 z = make_uint4(0,0,0,0);
      #pragma unroll
      for (int i = 0; i < 8; i++) *(uint4*)(dst + i*16) = z;
    }
  }
  CP_WAIT0();
  __syncthreads();

  // conv GEMM: 16 tok x 128 N per warp, K=128, ldmatrix fragments
  float acc[16][4];
  #pragma unroll
  for (int j = 0; j < 16; j++){ acc[j][0]=0; acc[j][1]=0; acc[j][2]=0; acc[j][3]=0; }

  uint32_t aAddr = sbase + LOFF_A + (warp*16 + (lane & 15))*APITCH + ((lane >> 4) << 4);
  uint32_t bAddr = sbase + LOFF_W + ((lane & 7) + ((lane >> 4) << 3))*APITCH
                 + (((lane >> 3) & 1) << 4);
  #pragma unroll
  for (int s = 0; s < 8; s++){
    uint32_t A[4];
    ldsm4(A, aAddr + s*32);
    #pragma unroll
    for (int p = 0; p < 8; p++){
      uint32_t Bv[4];
      ldsm4(Bv, bAddr + p*16*APITCH + s*32);
      mma16816(acc[2*p],   A[0], A[1], A[2], A[3], Bv[0], Bv[1]);
      mma16816(acc[2*p+1], A[0], A[1], A[2], A[3], Bv[2], Bv[3]);
    }
  }

  // gate (register-resident)
  uint32_t G[8][2];
  #pragma unroll
  for (int j = 0; j < 8; j++){
    int c0 = j*8 + q*2;
    float b1c = sCB[c0], b2c = sCB[c0+1], b1s = sCB[64+c0], b2s = sCB[64+c0+1];
    #pragma unroll
    for (int r = 0; r < 2; r++){
      float h1a = acc[j][2*r]     + b1c;
      float h1b = acc[j][2*r+1]   + b2c;
      float h2a = acc[j+8][2*r]   + b1s;
      float h2b = acc[j+8][2*r+1] + b2s;
      float ga = (__fdividef(2.f, 1.f + __expf(-2.f*h1a)) - 1.f)
               *  __fdividef(1.f, 1.f + __expf(-h2a));
      float gb = (__fdividef(2.f, 1.f + __expf(-2.f*h1b)) - 1.f)
               *  __fdividef(1.f, 1.f + __expf(-h2b));
      G[j][r] = pack2(ga, gb);
    }
  }

  // gate regs -> smem tile (padded pitch; conflict-free STS.32)
  {
    char* gbase = sm + LOFF_G + (warp*16)*RPITCH;
    #pragma unroll
    for (int j = 0; j < 8; j++){
      *(uint32_t*)(gbase + l4*RPITCH     + j*16 + q*4) = G[j][0];
      *(uint32_t*)(gbase + (l4+8)*RPITCH + j*16 + q*4) = G[j][1];
    }
  }

  // residual GEMM: A-frags from G regs, B via ldmatrix
  float r2[8][4];
  #pragma unroll
  for (int j = 0; j < 8; j++){ r2[j][0]=0; r2[j][1]=0; r2[j][2]=0; r2[j][3]=0; }
  uint32_t rAddr = sbase + LOFF_R + ((lane & 7) + ((lane >> 4) << 3))*RPITCH
                 + (((lane >> 3) & 1) << 4);
  #pragma unroll
  for (int s = 0; s < 4; s++){
    uint32_t a0 = G[2*s][0], a1 = G[2*s][1], a2 = G[2*s+1][0], a3 = G[2*s+1][1];
    #pragma unroll
    for (int p = 0; p < 4; p++){
      uint32_t Bv[4];
      ldsm4(Bv, rAddr + p*16*RPITCH + s*32);
      mma16816(r2[2*p],   a0, a1, a2, a3, Bv[0], Bv[1]);
      mma16816(r2[2*p+1], a0, a1, a2, a3, Bv[2], Bv[3]);
    }
  }

  __syncthreads();
  { // coalesced gates -> global
    char* gd = (char*)(g_gates + ((size_t)l*NTOK + tok0)*64);
    #pragma unroll
    for (int i = 0; i < 4; i++){
      int idx = tid + i*256, row = idx >> 3, c = idx & 7;
      *(uint4*)(gd + row*128 + c*16) = *(uint4*)(sm + LOFF_G + row*RPITCH + c*16);
    }
  }

  // writeback: xout = xin + res + rb
  {
    int tokA = tok0 + warp*16 + l4;
    int tokB = tokA + 8;
    #pragma unroll
    for (int j = 0; j < 8; j++){
      int c0 = j*8 + q*2;
      float rb0 = sRB[c0], rb1 = sRB[c0+1];
      float2 xa = *(const float2*)(xin + (size_t)tokA*64 + c0);
      float2 xb = *(const float2*)(xin + (size_t)tokB*64 + c0);
      *(float2*)(xout + (size_t)tokA*64 + c0) = make_float2(xa.x + r2[j][0] + rb0,
                                                            xa.y + r2[j][1] + rb1);
      *(float2*)(xout + (size_t)tokB*64 + c0) = make_float2(xb.x + r2[j][2] + rb0,
                                                            xb.y + r2[j][3] + rb1);
    }
  }
}

// ---------------- head kernel ------------------------------------------------------
#define HOFF_SKB 0
#define HOFF_B0  1024
#define HOFF_B1  2048
#define HOFF_G0  3072
#define HOFF_WC0 21504
#define HOFF_G1  58368
#define HOFF_WC1 76800
#define HOFF_W2  3072
#define HSMEM    113664
#define WPITCH2  272

__device__ __forceinline__ void head_stage1(uint32_t sbase, int gOff, int wOff,
                                            int l, int tok0, int tid){
  const char* gs = (const char*)(g_gates + ((size_t)l*NTOK + tok0)*64);
  #pragma unroll
  for (int i = 0; i < 4; i++){
    int idx = tid + i*256, row = idx >> 3, c = idx & 7;
    cp16(sbase + gOff + row*RPITCH + c*16, gs + row*128 + c*16);
  }
  const char* ws = (const char*)(g_skipw + (size_t)l*16384);
  #pragma unroll
  for (int i = 0; i < 8; i++){
    int idx = tid + i*256, row = idx >> 3, c = idx & 7;
    cp16(sbase + wOff + row*RPITCH + c*16, ws + row*128 + c*16);
  }
  CP_COMMIT();
}

__global__ __launch_bounds__(256, 1) void head_kernel(
    const float* __restrict__ b0, const float* __restrict__ b1,
    const int* __restrict__ wf, const int* __restrict__ lens)
{
  extern __shared__ char sm[];
  uint32_t sbase = s2u(sm);
  const int tid = threadIdx.x, warp = tid >> 5, lane = tid & 31;
  const int l4 = lane >> 2, q = lane & 3;
  const int tok0 = blockIdx.x * 128;

  float* sSKB = (float*)(sm + HOFF_SKB);
  float* sB0  = (float*)(sm + HOFF_B0);
  float* sB1  = (float*)(sm + HOFF_B1);
  sSKB[tid] = g_skipb[tid];
  sB0[tid]  = b0[tid];
  sB1[tid]  = b1[tid];

  // ---- phase 1: skip_sum, K=1920, double-buffered cp.async pipeline ----
  head_stage1(sbase, HOFF_G0, HOFF_WC0, 0, tok0, tid);
  head_stage1(sbase, HOFF_G1, HOFF_WC1, 1, tok0, tid);

  float acc[32][4];
  #pragma unroll
  for (int j = 0; j < 32; j++){ acc[j][0]=0; acc[j][1]=0; acc[j][2]=0; acc[j][3]=0; }

  const uint32_t aLane = (warp*16 + (lane & 15))*RPITCH + ((lane >> 4) << 4);
  const uint32_t bLane = ((lane & 7) + ((lane >> 4) << 3))*RPITCH + (((lane >> 3) & 1) << 4);

  for (int l = 0; l < NL; l++){
    int buf = l & 1;
    if (l < NL-1) CP_WAIT1(); else CP_WAIT0();
    __syncthreads();

    uint32_t aAddr = sbase + (buf ? HOFF_G1  : HOFF_G0)  + aLane;
    uint32_t bAddr = sbase + (buf ? HOFF_WC1 : HOFF_WC0) + bLane;
    #pragma unroll
    for (int s = 0; s < 4; s++){
      uint32_t A[4];
      ldsm4(A, aAddr + s*32);
      #pragma unroll
      for (int p = 0; p < 16; p++){
        uint32_t Bv[4];
        ldsm4(Bv, bAddr + p*16*RPITCH + s*32);
        mma16816(acc[2*p],   A[0], A[1], A[2], A[3], Bv[0], Bv[1]);
        mma16816(acc[2*p+1], A[0], A[1], A[2], A[3], Bv[2], Bv[3]);
      }
    }
    __syncthreads();
    if (l + 2 < NL)
      head_stage1(sbase, buf ? HOFF_G1 : HOFF_G0, buf ? HOFF_WC1 : HOFF_WC0,
                  l + 2, tok0, tid);
  }

  // pack P = bf16(acc + skipb)
  uint32_t P[32][2];
  #pragma unroll
  for (int j = 0; j < 32; j++){
    int c0 = j*8 + q*2;
    float s0 = sSKB[c0], s1 = sSKB[c0+1];
    P[j][0] = pack2(acc[j][0] + s0, acc[j][1] + s1);
    P[j][1] = pack2(acc[j][2] + s0, acc[j][3] + s1);
  }
  __syncthreads();

  const uint32_t bLane2 = ((lane & 7) + ((lane >> 4) << 3))*WPITCH2 + (((lane >> 3) & 1) << 4);

  // ---- phase 2: hid = relu(s @ w0^T + b0) ----
  #pragma unroll
  for (int j = 0; j < 32; j++){ acc[j][0]=0; acc[j][1]=0; acc[j][2]=0; acc[j][3]=0; }
  for (int kc = 0; kc < 2; kc++){
    {
      const char* ws = (const char*)g_w0t;
      #pragma unroll
      for (int i = 0; i < 16; i++){
        int idx = tid + i*256, row = idx >> 4, c = idx & 15;
        cp16(sbase + HOFF_W2 + row*WPITCH2 + c*16, ws + row*512 + kc*256 + c*16);
      }
      CP_COMMIT(); CP_WAIT0();
    }
    __syncthreads();
    #pragma unroll
    for (int s = 0; s < 8; s++){
      int S = kc*8 + s;
      uint32_t a0 = P[2*S][0], a1 = P[2*S][1], a2 = P[2*S+1][0], a3 = P[2*S+1][1];
      #pragma unroll
      for (int p = 0; p < 16; p++){
        uint32_t Bv[4];
        ldsm4(Bv, sbase + HOFF_W2 + bLane2 + p*16*WPITCH2 + s*32);
        mma16816(acc[2*p],   a0, a1, a2, a3, Bv[0], Bv[1]);
        mma16816(acc[2*p+1], a0, a1, a2, a3, Bv[2], Bv[3]);
      }
    }
    __syncthreads();
  }
  #pragma unroll
  for (int j = 0; j < 32; j++){
    int c0 = j*8 + q*2;
    float s0 = sB0[c0], s1 = sB0[c0+1];
    P[j][0] = pack2(fmaxf(acc[j][0] + s0, 0.f), fmaxf(acc[j][1] + s1, 0.f));
    P[j][1] = pack2(fmaxf(acc[j][2] + s0, 0.f), fmaxf(acc[j][3] + s1, 0.f));
  }

  // ---- phase 3: logits = hid @ w1^T ----
  #pragma unroll
  for (int j = 0; j < 32; j++){ acc[j][0]=0; acc[j][1]=0; acc[j][2]=0; acc[j][3]=0; }
  for (int kc = 0; kc < 2; kc++){
    {
      const char* ws = (const char*)g_w1t;
      #pragma unroll
      for (int i = 0; i < 16; i++){
        int idx = tid + i*256, row = idx >> 4, c = idx & 15;
        cp16(sbase + HOFF_W2 + row*WPITCH2 + c*16, ws + row*512 + kc*256 + c*16);
      }
      CP_COMMIT(); CP_WAIT0();
    }
    __syncthreads();
    #pragma unroll
    for (int s = 0; s < 8; s++){
      int S = kc*8 + s;
      uint32_t a0 = P[2*S][0], a1 = P[2*S][1], a2 = P[2*S+1][0], a3 = P[2*S+1][1];
      #pragma unroll
      for (int p = 0; p < 16; p++){
        uint32_t Bv[4];
        ldsm4(Bv, sbase + HOFF_W2 + bLane2 + p*16*WPITCH2 + s*32);
        mma16816(acc[2*p],   a0, a1, a2, a3, Bv[0], Bv[1]);
        mma16816(acc[2*p+1], a0, a1, a2, a3, Bv[2], Bv[3]);
      }
    }
    __syncthreads();
  }

  // ---- CE: per-token log-softmax over 256 logits ----
  float local = 0.f;
  int tokA = tok0 + warp*16 + l4;
  #pragma unroll
  for (int r = 0; r < 2; r++){
    int tok = tokA + r*8;
    int lab = wf[tok];
    float m = -1e30f;
    #pragma unroll
    for (int j = 0; j < 32; j++){
      int c0 = j*8 + q*2;
      float v0 = acc[j][2*r]   + sB1[c0];
      float v1 = acc[j][2*r+1] + sB1[c0+1];
      m = fmaxf(m, fmaxf(v0, v1));
    }
    m = fmaxf(m, __shfl_xor_sync(0xffffffffu, m, 1));
    m = fmaxf(m, __shfl_xor_sync(0xffffffffu, m, 2));
    float s = 0.f, lv = 0.f;
    #pragma unroll
    for (int j = 0; j < 32; j++){
      int c0 = j*8 + q*2;
      float v0 = acc[j][2*r]   + sB1[c0];
      float v1 = acc[j][2*r+1] + sB1[c0+1];
      s += __expf(v0 - m) + __expf(v1 - m);
      if (lab == c0)   lv += v0;
      if (lab == c0+1) lv += v1;
    }
    s  += __shfl_xor_sync(0xffffffffu, s, 1);
    s  += __shfl_xor_sync(0xffffffffu, s, 2);
    lv += __shfl_xor_sync(0xffffffffu, lv, 1);
    lv += __shfl_xor_sync(0xffffffffu, lv, 2);
    float ce = m + logf(s) - lv;
    int t = tok & (NT-1);
    int b = tok >> 13;
    if (q == 0 && t < lens[b]) local += ce;
  }
  #pragma unroll
  for (int off = 16; off; off >>= 1)
    local += __shfl_xor_sync(0xffffffffu, local, off);
  if (lane == 0) atomicAdd(&g_num, local);
}

__global__ void finalize_kernel(const int* __restrict__ lens, float* __restrict__ out){
  float denom = 0.f;
  for (int b = 0; b < NB; b++) denom += (float)lens[b];
  out[0] = g_num / fmaxf(denom, 1.f);
}

// ---------------- launcher ----------------------------------------------------------
extern "C" void kernel_launch(void* const* d_in, const int* in_sizes, int n_in,
                              void* d_out, int out_size)
{
  const int*   wf     = (const int*)d_in[0];
  const int*   lens   = (const int*)d_in[1];
  const float* emb    = (const float*)d_in[2];
  const float* conv_w = (const float*)d_in[3];
  const float* conv_b = (const float*)d_in[4];
  const float* res_w  = (const float*)d_in[5];
  const float* res_b  = (const float*)d_in[6];
  const float* skip_w = (const float*)d_in[7];
  const float* skip_b = (const float*)d_in[8];
  const float* w0     = (const float*)d_in[9];
  const float* b0     = (const float*)d_in[10];
  const float* w1     = (const float*)d_in[11];
  const float* b1     = (const float*)d_in[12];

  static const int dil[NL] = {1,2,4,8,16,32,64,128,256,512,
                              1,2,4,8,16,32,64,128,256,512,
                              1,2,4,8,16,32,64,128,256,512};

  cudaFuncSetAttribute(layer_kernel, cudaFuncAttributeMaxDynamicSharedMemorySize, LSMEM);
  cudaFuncSetAttribute(head_kernel,  cudaFuncAttributeMaxDynamicSharedMemorySize, HSMEM);

  prep_misc_kernel<<<1, NS>>>(skip_b);
  prep_w_kernel<<<4832, 256>>>(conv_w, res_w, skip_w, w0, w1);
  embed_kernel<<<NTOK/4, 256>>>(wf, emb);
  for (int i = 0; i < NL; i++)
    layer_kernel<<<NTOK/128, 256, LSMEM>>>(conv_b, res_b, i, dil[i], i & 1);
  head_kernel<<<NTOK/128, 256, HSMEM>>>(b0, b1, wf, lens);
  finalize_kernel<<<1, 1>>>(lens, (float*)d_out);
}

// round 6
// speedup vs baseline: 9.7728x; 1.2965x over previous
#include <cuda_runtime.h>
#include <cuda_bf16.h>
#include <math.h>
#include <stdint.h>

#define NB 4
#define NT 8192
#define NC 64
#define NS 256
#define NV 256
#define NL 30
#define NTOK (NB*NT)

// ---------------- device scratch ---------------------------------------------
__device__ __nv_bfloat16 g_x0[(size_t)NTOK*NC];         // residual stream (bf16)
__device__ __nv_bfloat16 g_x1[(size_t)NTOK*NC];
__device__ __nv_bfloat16 g_gates[(size_t)NL*NTOK*NC];   // [l][tok][64]
__device__ __nv_bfloat16 g_convw[NL*128*128];           // [l][f][k]
__device__ __nv_bfloat16 g_resw[NL*64*64];              // [l][o][k]
__device__ __nv_bfloat16 g_skipw[NL*256*64];            // [l][v][k]
__device__ __nv_bfloat16 g_w0t[256*256];                // [v][k]
__device__ __nv_bfloat16 g_w1t[256*256];                // [v][k]
__device__ float g_skipb[NS];
__device__ float g_num;

// ---------------- helpers ------------------------------------------------------
__device__ __forceinline__ uint32_t s2u(const void* p){
  uint32_t a;
  asm("{ .reg .u64 t; cvta.to.shared.u64 t, %1; cvt.u32.u64 %0, t; }" : "=r"(a) : "l"(p));
  return a;
}
__device__ __forceinline__ void mma16816(float* c, uint32_t a0, uint32_t a1,
                                         uint32_t a2, uint32_t a3,
                                         uint32_t b0, uint32_t b1){
  asm volatile("mma.sync.aligned.m16n8k16.row.col.f32.bf16.bf16.f32 "
    "{%0,%1,%2,%3}, {%4,%5,%6,%7}, {%8,%9}, {%0,%1,%2,%3};"
    : "+f"(c[0]), "+f"(c[1]), "+f"(c[2]), "+f"(c[3])
    : "r"(a0), "r"(a1), "r"(a2), "r"(a3), "r"(b0), "r"(b1));
}
__device__ __forceinline__ void ldsm4(uint32_t* r, uint32_t a){
  asm volatile("ldmatrix.sync.aligned.m8n8.x4.shared.b16 {%0,%1,%2,%3}, [%4];"
    : "=r"(r[0]), "=r"(r[1]), "=r"(r[2]), "=r"(r[3]) : "r"(a));
}
__device__ __forceinline__ void cp16(uint32_t d, const void* s){
  asm volatile("cp.async.ca.shared.global [%0], [%1], 16;" :: "r"(d), "l"(s));
}
// predicated copy: pred!=0 -> copy 16B, pred==0 -> zero-fill 16B
__device__ __forceinline__ void cp16z(uint32_t d, const void* s, int pred){
  asm volatile("{\n .reg .pred p;\n setp.ne.b32 p, %2, 0;\n"
    " @p  cp.async.ca.shared.global [%0], [%1], 16;\n"
    " @!p cp.async.ca.shared.global [%0], [%1], 16, 0;\n}"
    :: "r"(d), "l"(s), "r"(pred));
}
#define CP_COMMIT() asm volatile("cp.async.commit_group;" ::: "memory")
#define CP_WAIT0()  asm volatile("cp.async.wait_group 0;" ::: "memory")
#define CP_WAIT1()  asm volatile("cp.async.wait_group 1;" ::: "memory")

__device__ __forceinline__ uint32_t pack2(float a, float b){
  __nv_bfloat162 t = __floats2bfloat162_rn(a, b);
  return *(uint32_t*)&t;
}
__device__ __forceinline__ float tanh_ap(float x){
  float r;
  asm("tanh.approx.f32 %0, %1;" : "=f"(r) : "f"(x));
  return r;
}

// ---------------- prep ----------------------------------------------------------
__global__ void prep_w_kernel(const float* __restrict__ conv_w,
                              const float* __restrict__ res_w,
                              const float* __restrict__ skip_w,
                              const float* __restrict__ w0,
                              const float* __restrict__ w1){
  int idx = blockIdx.x*256 + threadIdx.x;
  if (idx < NL*128*128){
    int k = idx & 127, f = (idx>>7)&127, l = idx>>14;
    float v = (k < 64) ? conv_w[((l*2+1)*64 + k)*128 + f]
                       : conv_w[((l*2+0)*64 + (k-64))*128 + f];
    g_convw[((size_t)l*128 + f)*128 + k] = __float2bfloat16(v);
    return;
  }
  idx -= NL*128*128;
  if (idx < NL*64*64){
    int k = idx & 63, o = (idx>>6)&63, l = idx>>12;
    g_resw[((size_t)l*64 + o)*64 + k] = __float2bfloat16(res_w[((size_t)l*64 + k)*64 + o]);
    return;
  }
  idx -= NL*64*64;
  if (idx < NL*256*64){
    int k = idx & 63, v2 = (idx>>6)&255, l = idx>>14;
    g_skipw[((size_t)l*256 + v2)*64 + k] = __float2bfloat16(skip_w[((size_t)l*64 + k)*256 + v2]);
    return;
  }
  idx -= NL*256*64;
  if (idx < 256*256){
    int k = idx & 255, v2 = idx>>8;
    g_w0t[v2*256 + k] = __float2bfloat16(w0[k*256 + v2]);
    return;
  }
  idx -= 256*256;
  if (idx < 256*256){
    int k = idx & 255, v2 = idx>>8;
    g_w1t[v2*256 + k] = __float2bfloat16(w1[k*256 + v2]);
  }
}

__global__ void prep_misc_kernel(const float* __restrict__ skip_b){
  int s = threadIdx.x;
  float a = 0.f;
  #pragma unroll 6
  for (int l = 0; l < NL; l++) a += skip_b[l*NS + s];
  g_skipb[s] = a;
  if (s == 0) g_num = 0.f;
}

__global__ void embed_kernel(const int* __restrict__ wf, const float* __restrict__ emb){
  int tid = threadIdx.x;
  int tok = blockIdx.x*4 + (tid >> 6);
  int c   = tid & 63;
  int t   = tok & (NT-1);
  int lab = (t == 0) ? 128 : wf[tok-1];
  g_x0[(size_t)tok*NC + c] = __float2bfloat16(emb[lab*NC + c]);
}

// ---------------- layer kernel ---------------------------------------------------
#define LOFF_CB 0
#define LOFF_RB 512
#define LOFF_A  768
#define LOFF_W  35584
#define LOFF_R  70400
#define LOFF_G  79616
#define LSMEM   98048
#define APITCH  272
#define RPITCH  144

__global__ __launch_bounds__(256, 2) void layer_kernel(
    const float* __restrict__ conv_b, const float* __restrict__ res_b,
    int l, int d, int flip)
{
  extern __shared__ char sm[];
  uint32_t sbase = s2u(sm);
  const __nv_bfloat16* __restrict__ xin  = flip ? g_x1 : g_x0;
  __nv_bfloat16* __restrict__       xout = flip ? g_x0 : g_x1;

  const int tid = threadIdx.x, warp = tid >> 5, lane = tid & 31;
  const int l4 = lane >> 2, q = lane & 3;
  const int tok0 = blockIdx.x * 128;

  // ---- async staging: everything via cp.async ----
  {
    // biases (raw fp32 bytes)
    if (tid < 32) cp16(sbase + LOFF_CB + tid*16, (const char*)(conv_b + l*128) + tid*16);
    else if (tid < 48) cp16(sbase + LOFF_RB + (tid-32)*16, (const char*)(res_b + l*64) + (tid-32)*16);
    // conv weights 128x128 bf16
    const char* wsrc = (const char*)(g_convw + (size_t)l*16384);
    #pragma unroll
    for (int i = 0; i < 8; i++){
      int idx = tid + i*256, row = idx >> 4, c = idx & 15;
      cp16(sbase + LOFF_W + row*APITCH + c*16, wsrc + row*256 + c*16);
    }
    // res weights 64x64 bf16
    const char* rsrc = (const char*)(g_resw + (size_t)l*4096);
    #pragma unroll
    for (int i = 0; i < 2; i++){
      int idx = tid + i*256, row = idx >> 3, c = idx & 7;
      cp16(sbase + LOFF_R + row*RPITCH + c*16, rsrc + row*128 + c*16);
    }
    // A tile: row tok, first 128B = x[t], second 128B = x[t-d] (zfill if t<d)
    {
      int r = tid >> 1, h = tid & 1;
      int tok = tok0 + r;
      int t = tok & (NT-1);
      int ok = (h == 0) | (t >= d);
      const char* src = (const char*)(xin + (size_t)(tok - (h ? d : 0))*64);
      uint32_t dst = sbase + LOFF_A + r*APITCH + h*128;
      #pragma unroll
      for (int i = 0; i < 8; i++) cp16z(dst + i*16, src + i*16, ok);
    }
    CP_COMMIT();
  }
  CP_WAIT0();
  __syncthreads();

  // ---- conv GEMM: 16 tok x 128 N per warp, K=128 ----
  float acc[16][4];
  #pragma unroll
  for (int j = 0; j < 16; j++){ acc[j][0]=0; acc[j][1]=0; acc[j][2]=0; acc[j][3]=0; }

  uint32_t aAddr = sbase + LOFF_A + (warp*16 + (lane & 15))*APITCH + ((lane >> 4) << 4);
  uint32_t bAddr = sbase + LOFF_W + ((lane & 7) + ((lane >> 4) << 3))*APITCH
                 + (((lane >> 3) & 1) << 4);
  #pragma unroll
  for (int s = 0; s < 8; s++){
    uint32_t A[4];
    ldsm4(A, aAddr + s*32);
    #pragma unroll
    for (int p = 0; p < 8; p++){
      uint32_t Bv[4];
      ldsm4(Bv, bAddr + p*16*APITCH + s*32);
      mma16816(acc[2*p],   A[0], A[1], A[2], A[3], Bv[0], Bv[1]);
      mma16816(acc[2*p+1], A[0], A[1], A[2], A[3], Bv[2], Bv[3]);
    }
  }

  // ---- gate (tanh.approx; sigmoid(x)=0.5*tanh(x/2)+0.5) ----
  const float* sCB = (const float*)(sm + LOFF_CB);
  uint32_t G[8][2];
  #pragma unroll
  for (int j = 0; j < 8; j++){
    int c0 = j*8 + q*2;
    float b1c = sCB[c0], b2c = sCB[c0+1], b1s = sCB[64+c0], b2s = sCB[64+c0+1];
    #pragma unroll
    for (int r = 0; r < 2; r++){
      float h1a = acc[j][2*r]     + b1c;
      float h1b = acc[j][2*r+1]   + b2c;
      float h2a = acc[j+8][2*r]   + b1s;
      float h2b = acc[j+8][2*r+1] + b2s;
      float ga = tanh_ap(h1a) * fmaf(0.5f, tanh_ap(0.5f*h2a), 0.5f);
      float gb = tanh_ap(h1b) * fmaf(0.5f, tanh_ap(0.5f*h2b), 0.5f);
      G[j][r] = pack2(ga, gb);
    }
  }

  // gate regs -> smem G tile
  {
    char* gbase = sm + LOFF_G + (warp*16)*RPITCH;
    #pragma unroll
    for (int j = 0; j < 8; j++){
      *(uint32_t*)(gbase + l4*RPITCH     + j*16 + q*4) = G[j][0];
      *(uint32_t*)(gbase + (l4+8)*RPITCH + j*16 + q*4) = G[j][1];
    }
  }
  __syncthreads();

  // coalesced gates -> global
  {
    char* gd = (char*)(g_gates + ((size_t)l*NTOK + tok0)*64);
    #pragma unroll
    for (int i = 0; i < 4; i++){
      int idx = tid + i*256, row = idx >> 3, c = idx & 7;
      *(uint4*)(gd + row*128 + c*16) = *(uint4*)(sm + LOFF_G + row*RPITCH + c*16);
    }
  }

  // ---- residual GEMM: A-frags from G regs ----
  float r2[8][4];
  #pragma unroll
  for (int j = 0; j < 8; j++){ r2[j][0]=0; r2[j][1]=0; r2[j][2]=0; r2[j][3]=0; }
  uint32_t rAddr = sbase + LOFF_R + ((lane & 7) + ((lane >> 4) << 3))*RPITCH
                 + (((lane >> 3) & 1) << 4);
  #pragma unroll
  for (int s = 0; s < 4; s++){
    uint32_t a0 = G[2*s][0], a1 = G[2*s][1], a2 = G[2*s+1][0], a3 = G[2*s+1][1];
    #pragma unroll
    for (int p = 0; p < 4; p++){
      uint32_t Bv[4];
      ldsm4(Bv, rAddr + p*16*RPITCH + s*32);
      mma16816(r2[2*p],   a0, a1, a2, a3, Bv[0], Bv[1]);
      mma16816(r2[2*p+1], a0, a1, a2, a3, Bv[2], Bv[3]);
    }
  }

  // ---- xout = xin(smem A, first half) + res + rb, packed bf16 ----
  __syncthreads();   // all G smem reads (gates STG) complete before overwrite
  {
    const float* sRB = (const float*)(sm + LOFF_RB);
    const char* aRow = sm + LOFF_A + (warp*16)*APITCH;
    char* gRow = sm + LOFF_G + (warp*16)*RPITCH;
    #pragma unroll
    for (int j = 0; j < 8; j++){
      int c0 = j*8 + q*2;
      float rb0 = sRB[c0], rb1 = sRB[c0+1];
      #pragma unroll
      for (int r = 0; r < 2; r++){
        int row = l4 + 8*r;
        uint32_t xp = *(const uint32_t*)(aRow + row*APITCH + j*16 + q*4);
        __nv_bfloat162 xb = *(__nv_bfloat162*)&xp;
        float o0 = __bfloat162float(xb.x) + r2[j][2*r]   + rb0;
        float o1 = __bfloat162float(xb.y) + r2[j][2*r+1] + rb1;
        *(uint32_t*)(gRow + row*RPITCH + j*16 + q*4) = pack2(o0, o1);
      }
    }
  }
  __syncthreads();
  { // coalesced xout -> global
    char* xo = (char*)(xout + (size_t)tok0*64);
    #pragma unroll
    for (int i = 0; i < 4; i++){
      int idx = tid + i*256, row = idx >> 3, c = idx & 7;
      *(uint4*)(xo + row*128 + c*16) = *(uint4*)(sm + LOFF_G + row*RPITCH + c*16);
    }
  }
}

// ---------------- head kernel ------------------------------------------------------
#define HOFF_SKB 0
#define HOFF_B0  1024
#define HOFF_B1  2048
#define HOFF_G0  3072
#define HOFF_WC0 21504
#define HOFF_G1  58368
#define HOFF_WC1 76800
#define HOFF_W2  3072
#define HSMEM    113664
#define WPITCH2  272

__device__ __forceinline__ void head_stage1(uint32_t sbase, int gOff, int wOff,
                                            int l, int tok0, int tid){
  const char* gs = (const char*)(g_gates + ((size_t)l*NTOK + tok0)*64);
  #pragma unroll
  for (int i = 0; i < 4; i++){
    int idx = tid + i*256, row = idx >> 3, c = idx & 7;
    cp16(sbase + gOff + row*RPITCH + c*16, gs + row*128 + c*16);
  }
  const char* ws = (const char*)(g_skipw + (size_t)l*16384);
  #pragma unroll
  for (int i = 0; i < 8; i++){
    int idx = tid + i*256, row = idx >> 3, c = idx & 7;
    cp16(sbase + wOff + row*RPITCH + c*16, ws + row*128 + c*16);
  }
  CP_COMMIT();
}

__global__ __launch_bounds__(256, 1) void head_kernel(
    const float* __restrict__ b0, const float* __restrict__ b1,
    const int* __restrict__ wf, const int* __restrict__ lens)
{
  extern __shared__ char sm[];
  uint32_t sbase = s2u(sm);
  const int tid = threadIdx.x, warp = tid >> 5, lane = tid & 31;
  const int l4 = lane >> 2, q = lane & 3;
  const int tok0 = blockIdx.x * 128;

  float* sSKB = (float*)(sm + HOFF_SKB);
  float* sB0  = (float*)(sm + HOFF_B0);
  float* sB1  = (float*)(sm + HOFF_B1);
  sSKB[tid] = g_skipb[tid];
  sB0[tid]  = b0[tid];
  sB1[tid]  = b1[tid];

  // ---- phase 1: skip_sum, K=1920, double-buffered cp.async pipeline ----
  head_stage1(sbase, HOFF_G0, HOFF_WC0, 0, tok0, tid);
  head_stage1(sbase, HOFF_G1, HOFF_WC1, 1, tok0, tid);

  float acc[32][4];
  #pragma unroll
  for (int j = 0; j < 32; j++){ acc[j][0]=0; acc[j][1]=0; acc[j][2]=0; acc[j][3]=0; }

  const uint32_t aLane = (warp*16 + (lane & 15))*RPITCH + ((lane >> 4) << 4);
  const uint32_t bLane = ((lane & 7) + ((lane >> 4) << 3))*RPITCH + (((lane >> 3) & 1) << 4);

  for (int l = 0; l < NL; l++){
    int buf = l & 1;
    if (l < NL-1) CP_WAIT1(); else CP_WAIT0();
    __syncthreads();

    uint32_t aAddr = sbase + (buf ? HOFF_G1  : HOFF_G0)  + aLane;
    uint32_t bAddr = sbase + (buf ? HOFF_WC1 : HOFF_WC0) + bLane;
    #pragma unroll
    for (int s = 0; s < 4; s++){
      uint32_t A[4];
      ldsm4(A, aAddr + s*32);
      #pragma unroll
      for (int p = 0; p < 16; p++){
        uint32_t Bv[4];
        ldsm4(Bv, bAddr + p*16*RPITCH + s*32);
        mma16816(acc[2*p],   A[0], A[1], A[2], A[3], Bv[0], Bv[1]);
        mma16816(acc[2*p+1], A[0], A[1], A[2], A[3], Bv[2], Bv[3]);
      }
    }
    __syncthreads();
    if (l + 2 < NL)
      head_stage1(sbase, buf ? HOFF_G1 : HOFF_G0, buf ? HOFF_WC1 : HOFF_WC0,
                  l + 2, tok0, tid);
  }

  // pack P = bf16(acc + skipb)
  uint32_t P[32][2];
  #pragma unroll
  for (int j = 0; j < 32; j++){
    int c0 = j*8 + q*2;
    float s0 = sSKB[c0], s1 = sSKB[c0+1];
    P[j][0] = pack2(acc[j][0] + s0, acc[j][1] + s1);
    P[j][1] = pack2(acc[j][2] + s0, acc[j][3] + s1);
  }
  __syncthreads();

  const uint32_t bLane2 = ((lane & 7) + ((lane >> 4) << 3))*WPITCH2 + (((lane >> 3) & 1) << 4);

  // ---- phase 2: hid = relu(s @ w0^T + b0) ----
  #pragma unroll
  for (int j = 0; j < 32; j++){ acc[j][0]=0; acc[j][1]=0; acc[j][2]=0; acc[j][3]=0; }
  for (int kc = 0; kc < 2; kc++){
    {
      const char* ws = (const char*)g_w0t;
      #pragma unroll
      for (int i = 0; i < 16; i++){
        int idx = tid + i*256, row = idx >> 4, c = idx & 15;
        cp16(sbase + HOFF_W2 + row*WPITCH2 + c*16, ws + row*512 + kc*256 + c*16);
      }
      CP_COMMIT(); CP_WAIT0();
    }
    __syncthreads();
    #pragma unroll
    for (int s = 0; s < 8; s++){
      int S = kc*8 + s;
      uint32_t a0 = P[2*S][0], a1 = P[2*S][1], a2 = P[2*S+1][0], a3 = P[2*S+1][1];
      #pragma unroll
      for (int p = 0; p < 16; p++){
        uint32_t Bv[4];
        ldsm4(Bv, sbase + HOFF_W2 + bLane2 + p*16*WPITCH2 + s*32);
        mma16816(acc[2*p],   a0, a1, a2, a3, Bv[0], Bv[1]);
        mma16816(acc[2*p+1], a0, a1, a2, a3, Bv[2], Bv[3]);
      }
    }
    __syncthreads();
  }
  #pragma unroll
  for (int j = 0; j < 32; j++){
    int c0 = j*8 + q*2;
    float s0 = sB0[c0], s1 = sB0[c0+1];
    P[j][0] = pack2(fmaxf(acc[j][0] + s0, 0.f), fmaxf(acc[j][1] + s1, 0.f));
    P[j][1] = pack2(fmaxf(acc[j][2] + s0, 0.f), fmaxf(acc[j][3] + s1, 0.f));
  }

  // ---- phase 3: logits = hid @ w1^T ----
  #pragma unroll
  for (int j = 0; j < 32; j++){ acc[j][0]=0; acc[j][1]=0; acc[j][2]=0; acc[j][3]=0; }
  for (int kc = 0; kc < 2; kc++){
    {
      const char* ws = (const char*)g_w1t;
      #pragma unroll
      for (int i = 0; i < 16; i++){
        int idx = tid + i*256, row = idx >> 4, c = idx & 15;
        cp16(sbase + HOFF_W2 + row*WPITCH2 + c*16, ws + row*512 + kc*256 + c*16);
      }
      CP_COMMIT(); CP_WAIT0();
    }
    __syncthreads();
    #pragma unroll
    for (int s = 0; s < 8; s++){
      int S = kc*8 + s;
      uint32_t a0 = P[2*S][0], a1 = P[2*S][1], a2 = P[2*S+1][0], a3 = P[2*S+1][1];
      #pragma unroll
      for (int p = 0; p < 16; p++){
        uint32_t Bv[4];
        ldsm4(Bv, sbase + HOFF_W2 + bLane2 + p*16*WPITCH2 + s*32);
        mma16816(acc[2*p],   a0, a1, a2, a3, Bv[0], Bv[1]);
        mma16816(acc[2*p+1], a0, a1, a2, a3, Bv[2], Bv[3]);
      }
    }
    __syncthreads();
  }

  // ---- CE: per-token log-softmax over 256 logits ----
  float local = 0.f;
  int tokA = tok0 + warp*16 + l4;
  #pragma unroll
  for (int r = 0; r < 2; r++){
    int tok = tokA + r*8;
    int lab = wf[tok];
    float m = -1e30f;
    #pragma unroll
    for (int j = 0; j < 32; j++){
      int c0 = j*8 + q*2;
      float v0 = acc[j][2*r]   + sB1[c0];
      float v1 = acc[j][2*r+1] + sB1[c0+1];
      m = fmaxf(m, fmaxf(v0, v1));
    }
    m = fmaxf(m, __shfl_xor_sync(0xffffffffu, m, 1));
    m = fmaxf(m, __shfl_xor_sync(0xffffffffu, m, 2));
    float s = 0.f, lv = 0.f;
    #pragma unroll
    for (int j = 0; j < 32; j++){
      int c0 = j*8 + q*2;
      float v0 = acc[j][2*r]   + sB1[c0];
      float v1 = acc[j][2*r+1] + sB1[c0+1];
      s += __expf(v0 - m) + __expf(v1 - m);
      if (lab == c0)   lv += v0;
      if (lab == c0+1) lv += v1;
    }
    s  += __shfl_xor_sync(0xffffffffu, s, 1);
    s  += __shfl_xor_sync(0xffffffffu, s, 2);
    lv += __shfl_xor_sync(0xffffffffu, lv, 1);
    lv += __shfl_xor_sync(0xffffffffu, lv, 2);
    float ce = m + logf(s) - lv;
    int t = tok & (NT-1);
    int b = tok >> 13;
    if (q == 0 && t < lens[b]) local += ce;
  }
  #pragma unroll
  for (int off = 16; off; off >>= 1)
    local += __shfl_xor_sync(0xffffffffu, local, off);
  if (lane == 0) atomicAdd(&g_num, local);
}

__global__ void finalize_kernel(const int* __restrict__ lens, float* __restrict__ out){
  float denom = 0.f;
  for (int b = 0; b < NB; b++) denom += (float)lens[b];
  out[0] = g_num / fmaxf(denom, 1.f);
}

// ---------------- launcher ----------------------------------------------------------
extern "C" void kernel_launch(void* const* d_in, const int* in_sizes, int n_in,
                              void* d_out, int out_size)
{
  const int*   wf     = (const int*)d_in[0];
  const int*   lens   = (const int*)d_in[1];
  const float* emb    = (const float*)d_in[2];
  const float* conv_w = (const float*)d_in[3];
  const float* conv_b = (const float*)d_in[4];
  const float* res_w  = (const float*)d_in[5];
  const float* res_b  = (const float*)d_in[6];
  const float* skip_w = (const float*)d_in[7];
  const float* skip_b = (const float*)d_in[8];
  const float* w0     = (const float*)d_in[9];
  const float* b0     = (const float*)d_in[10];
  const float* w1     = (const float*)d_in[11];
  const float* b1     = (const float*)d_in[12];

  static const int dil[NL] = {1,2,4,8,16,32,64,128,256,512,
                              1,2,4,8,16,32,64,128,256,512,
                              1,2,4,8,16,32,64,128,256,512};

  cudaFuncSetAttribute(layer_kernel, cudaFuncAttributeMaxDynamicSharedMemorySize, LSMEM);
  cudaFuncSetAttribute(head_kernel,  cudaFuncAttributeMaxDynamicSharedMemorySize, HSMEM);

  prep_misc_kernel<<<1, NS>>>(skip_b);
  prep_w_kernel<<<4832, 256>>>(conv_w, res_w, skip_w, w0, w1);
  embed_kernel<<<NTOK/4, 256>>>(wf, emb);
  for (int i = 0; i < NL; i++)
    layer_kernel<<<NTOK/128, 256, LSMEM>>>(conv_b, res_b, i, dil[i], i & 1);
  head_kernel<<<NTOK/128, 256, HSMEM>>>(b0, b1, wf, lens);
  finalize_kernel<<<1, 1>>>(lens, (float*)d_out);
}

// round 7
// speedup vs baseline: 12.2021x; 1.2486x over previous
#include <cuda_runtime.h>
#include <cuda_bf16.h>
#include <math.h>
#include <stdint.h>

#define NB 4
#define NT 8192
#define NC 64
#define NS 256
#define NV 256
#define NL 30
#define NTOK (NB*NT)

// ---------------- device scratch ---------------------------------------------
__device__ __nv_bfloat16 g_xh[(size_t)(NL+1)*NTOK*NC];  // per-layer x history
__device__ __nv_bfloat16 g_gates[(size_t)NL*NTOK*NC];   // [l][tok][64]
__device__ __nv_bfloat16 g_convw[NL*128*128];           // [l][f][k]
__device__ __nv_bfloat16 g_resw[NL*64*64];              // [l][o][k]
__device__ __nv_bfloat16 g_skipw[NL*256*64];            // [l][v][k]
__device__ __nv_bfloat16 g_w0t[256*256];                // [v][k]
__device__ __nv_bfloat16 g_w1t[256*256];                // [v][k]
__device__ float g_skipb[NS];
__device__ float g_num;
__device__ int   g_flags[256];

// ---------------- helpers ------------------------------------------------------
__device__ __forceinline__ uint32_t s2u(const void* p){
  uint32_t a;
  asm("{ .reg .u64 t; cvta.to.shared.u64 t, %1; cvt.u32.u64 %0, t; }" : "=r"(a) : "l"(p));
  return a;
}
__device__ __forceinline__ void mma16816(float* c, uint32_t a0, uint32_t a1,
                                         uint32_t a2, uint32_t a3,
                                         uint32_t b0, uint32_t b1){
  asm volatile("mma.sync.aligned.m16n8k16.row.col.f32.bf16.bf16.f32 "
    "{%0,%1,%2,%3}, {%4,%5,%6,%7}, {%8,%9}, {%0,%1,%2,%3};"
    : "+f"(c[0]), "+f"(c[1]), "+f"(c[2]), "+f"(c[3])
    : "r"(a0), "r"(a1), "r"(a2), "r"(a3), "r"(b0), "r"(b1));
}
__device__ __forceinline__ void ldsm4(uint32_t* r, uint32_t a){
  asm volatile("ldmatrix.sync.aligned.m8n8.x4.shared.b16 {%0,%1,%2,%3}, [%4];"
    : "=r"(r[0]), "=r"(r[1]), "=r"(r[2]), "=r"(r[3]) : "r"(a));
}
__device__ __forceinline__ void cp16(uint32_t d, const void* s){
  asm volatile("cp.async.ca.shared.global [%0], [%1], 16;" :: "r"(d), "l"(s));
}
__device__ __forceinline__ void cp16g(uint32_t d, const void* s){
  asm volatile("cp.async.cg.shared.global [%0], [%1], 16;" :: "r"(d), "l"(s));
}
__device__ __forceinline__ void cp16zg(uint32_t d, const void* s, int pred){
  asm volatile("{\n .reg .pred p;\n setp.ne.b32 p, %2, 0;\n"
    " @p  cp.async.cg.shared.global [%0], [%1], 16;\n"
    " @!p cp.async.cg.shared.global [%0], [%1], 16, 0;\n}"
    :: "r"(d), "l"(s), "r"(pred));
}
#define CP_COMMIT() asm volatile("cp.async.commit_group;" ::: "memory")
#define CP_WAIT0()  asm volatile("cp.async.wait_group 0;" ::: "memory")
#define CP_WAIT1()  asm volatile("cp.async.wait_group 1;" ::: "memory")

__device__ __forceinline__ uint32_t pack2(float a, float b){
  __nv_bfloat162 t = __floats2bfloat162_rn(a, b);
  return *(uint32_t*)&t;
}
__device__ __forceinline__ float tanh_ap(float x){
  float r;
  asm("tanh.approx.f32 %0, %1;" : "=f"(r) : "f"(x));
  return r;
}
__device__ __forceinline__ int ld_acq(const int* p){
  int v;
  asm volatile("ld.acquire.gpu.global.b32 %0, [%1];" : "=r"(v) : "l"(p) : "memory");
  return v;
}
__device__ __forceinline__ void red_rel(int* p){
  asm volatile("red.release.gpu.global.add.s32 [%0], %1;" :: "l"(p), "r"(1) : "memory");
}

// ---------------- prep ----------------------------------------------------------
__global__ void prep_w_kernel(const float* __restrict__ conv_w,
                              const float* __restrict__ res_w,
                              const float* __restrict__ skip_w,
                              const float* __restrict__ w0,
                              const float* __restrict__ w1){
  int idx = blockIdx.x*256 + threadIdx.x;
  if (idx < NL*128*128){
    int k = idx & 127, f = (idx>>7)&127, l = idx>>14;
    float v = (k < 64) ? conv_w[((l*2+1)*64 + k)*128 + f]
                       : conv_w[((l*2+0)*64 + (k-64))*128 + f];
    g_convw[((size_t)l*128 + f)*128 + k] = __float2bfloat16(v);
    return;
  }
  idx -= NL*128*128;
  if (idx < NL*64*64){
    int k = idx & 63, o = (idx>>6)&63, l = idx>>12;
    g_resw[((size_t)l*64 + o)*64 + k] = __float2bfloat16(res_w[((size_t)l*64 + k)*64 + o]);
    return;
  }
  idx -= NL*64*64;
  if (idx < NL*256*64){
    int k = idx & 63, v2 = (idx>>6)&255, l = idx>>14;
    g_skipw[((size_t)l*256 + v2)*64 + k] = __float2bfloat16(skip_w[((size_t)l*64 + k)*256 + v2]);
    return;
  }
  idx -= NL*256*64;
  if (idx < 256*256){
    int k = idx & 255, v2 = idx>>8;
    g_w0t[v2*256 + k] = __float2bfloat16(w0[k*256 + v2]);
    return;
  }
  idx -= 256*256;
  if (idx < 256*256){
    int k = idx & 255, v2 = idx>>8;
    g_w1t[v2*256 + k] = __float2bfloat16(w1[k*256 + v2]);
  }
}

__global__ void prep_misc_kernel(const float* __restrict__ skip_b){
  int s = threadIdx.x;
  float a = 0.f;
  #pragma unroll 6
  for (int l = 0; l < NL; l++) a += skip_b[l*NS + s];
  g_skipb[s] = a;
  g_flags[s] = 0;
  if (s == 0) g_num = 0.f;
}

__global__ void embed_kernel(const int* __restrict__ wf, const float* __restrict__ emb){
  int tid = threadIdx.x;
  int tok = blockIdx.x*4 + (tid >> 6);
  int c   = tid & 63;
  int t   = tok & (NT-1);
  int lab = (t == 0) ? 128 : wf[tok-1];
  g_xh[(size_t)tok*NC + c] = __float2bfloat16(emb[lab*NC + c]);
}

// ---------------- fused 30-layer kernel -----------------------------------------
#define LOFF_A  1536
#define LOFF_W  36352
#define LOFF_R  71168
#define LOFF_G  80384
#define LSMEM   98816
#define APITCH  272
#define RPITCH  144

__device__ __forceinline__ void stage_weights(uint32_t sbase, int l, int buf, int tid,
                                              const float* conv_b, const float* res_b){
  if (tid < 32) cp16(sbase + buf*768 + tid*16, (const char*)(conv_b + l*128) + tid*16);
  else if (tid < 48) cp16(sbase + buf*768 + 512 + (tid-32)*16,
                          (const char*)(res_b + l*64) + (tid-32)*16);
  const char* wsrc = (const char*)(g_convw + (size_t)l*16384);
  #pragma unroll
  for (int i = 0; i < 8; i++){
    int idx = tid + i*256, row = idx >> 4, c = idx & 15;
    cp16(sbase + LOFF_W + row*APITCH + c*16, wsrc + row*256 + c*16);
  }
  const char* rsrc = (const char*)(g_resw + (size_t)l*4096);
  #pragma unroll
  for (int i = 0; i < 2; i++){
    int idx = tid + i*256, row = idx >> 3, c = idx & 7;
    cp16(sbase + LOFF_R + row*RPITCH + c*16, rsrc + row*128 + c*16);
  }
}

__device__ __forceinline__ void stage_ashift(uint32_t sbase, const __nv_bfloat16* xsrc,
                                             int dL, int tok0, int tid){
  #pragma unroll
  for (int i = 0; i < 4; i++){
    int idx = tid + i*256;
    int row = idx >> 3, c = idx & 7;
    int tok = tok0 + row, t = tok & (NT-1);
    cp16zg(sbase + LOFF_A + row*APITCH + 128 + c*16,
           (const char*)(xsrc + (long)(tok - dL)*64) + c*16, t >= dL);
  }
}

__global__ __launch_bounds__(256, 2) void layers_kernel(
    const float* __restrict__ conv_b, const float* __restrict__ res_b)
{
  extern __shared__ char sm[];
  uint32_t sbase = s2u(sm);
  const int tid = threadIdx.x, warp = tid >> 5, lane = tid & 31;
  const int l4 = lane >> 2, q = lane & 3;
  const int cta = blockIdx.x;
  const int tok0 = cta * 128;

  // ---- prologue: stage layer-0 weights/biases + full A ----
  stage_weights(sbase, 0, 0, tid, conv_b, res_b);
  {
    const char* xs = (const char*)(g_xh + (size_t)tok0*64);
    #pragma unroll
    for (int i = 0; i < 4; i++){
      int idx = tid + i*256, row = idx >> 3, c = idx & 7;
      cp16g(sbase + LOFF_A + row*APITCH + c*16, xs + row*128 + c*16);
    }
    // second half: x[t-1] (d=1)
    #pragma unroll
    for (int i = 0; i < 4; i++){
      int idx = tid + i*256, row = idx >> 3, c = idx & 7;
      int tok = tok0 + row, t = tok & (NT-1);
      cp16zg(sbase + LOFF_A + row*APITCH + 128 + c*16,
             (const char*)(g_xh + (long)(tok - 1)*64) + c*16, t >= 1);
    }
  }
  CP_COMMIT();

  const uint32_t aAddr = sbase + LOFF_A + (warp*16 + (lane & 15))*APITCH + ((lane >> 4) << 4);
  const uint32_t bAddr = sbase + LOFF_W + ((lane & 7) + ((lane >> 4) << 3))*APITCH
                       + (((lane >> 3) & 1) << 4);
  const uint32_t rAddr = sbase + LOFF_R + ((lane & 7) + ((lane >> 4) << 3))*RPITCH
                       + (((lane >> 3) & 1) << 4);

  for (int l = 0; l < NL; l++){
    const int buf = l & 1;
    CP_WAIT0();
    __syncthreads();

    // ---- conv GEMM: 16 tok x 128 N per warp, K=128 ----
    float acc[16][4];
    #pragma unroll
    for (int j = 0; j < 16; j++){ acc[j][0]=0; acc[j][1]=0; acc[j][2]=0; acc[j][3]=0; }
    #pragma unroll
    for (int s = 0; s < 8; s++){
      uint32_t A[4];
      ldsm4(A, aAddr + s*32);
      #pragma unroll
      for (int p = 0; p < 8; p++){
        uint32_t Bv[4];
        ldsm4(Bv, bAddr + p*16*APITCH + s*32);
        mma16816(acc[2*p],   A[0], A[1], A[2], A[3], Bv[0], Bv[1]);
        mma16816(acc[2*p+1], A[0], A[1], A[2], A[3], Bv[2], Bv[3]);
      }
    }

    // ---- gate ----
    const float* sCB = (const float*)(sm + buf*768);
    uint32_t G[8][2];
    #pragma unroll
    for (int j = 0; j < 8; j++){
      int c0 = j*8 + q*2;
      float b1c = sCB[c0], b2c = sCB[c0+1], b1s = sCB[64+c0], b2s = sCB[64+c0+1];
      #pragma unroll
      for (int r = 0; r < 2; r++){
        float h1a = acc[j][2*r]     + b1c;
        float h1b = acc[j][2*r+1]   + b2c;
        float h2a = acc[j+8][2*r]   + b1s;
        float h2b = acc[j+8][2*r+1] + b2s;
        float ga = tanh_ap(h1a) * fmaf(0.5f, tanh_ap(0.5f*h2a), 0.5f);
        float gb = tanh_ap(h1b) * fmaf(0.5f, tanh_ap(0.5f*h2b), 0.5f);
        G[j][r] = pack2(ga, gb);
      }
    }

    // gate regs -> smem G tile
    {
      char* gbase = sm + LOFF_G + (warp*16)*RPITCH;
      #pragma unroll
      for (int j = 0; j < 8; j++){
        *(uint32_t*)(gbase + l4*RPITCH     + j*16 + q*4) = G[j][0];
        *(uint32_t*)(gbase + (l4+8)*RPITCH + j*16 + q*4) = G[j][1];
      }
    }
    __syncthreads();

    // coalesced gates -> global
    {
      char* gd = (char*)(g_gates + ((size_t)l*NTOK + tok0)*64);
      #pragma unroll
      for (int i = 0; i < 4; i++){
        int idx = tid + i*256, row = idx >> 3, c = idx & 7;
        *(uint4*)(gd + row*128 + c*16) = *(uint4*)(sm + LOFF_G + row*RPITCH + c*16);
      }
    }

    // ---- residual GEMM ----
    float r2[8][4];
    #pragma unroll
    for (int j = 0; j < 8; j++){ r2[j][0]=0; r2[j][1]=0; r2[j][2]=0; r2[j][3]=0; }
    #pragma unroll
    for (int s = 0; s < 4; s++){
      uint32_t a0 = G[2*s][0], a1 = G[2*s][1], a2 = G[2*s+1][0], a3 = G[2*s+1][1];
      #pragma unroll
      for (int p = 0; p < 4; p++){
        uint32_t Bv[4];
        ldsm4(Bv, rAddr + p*16*RPITCH + s*32);
        mma16816(r2[2*p],   a0, a1, a2, a3, Bv[0], Bv[1]);
        mma16816(r2[2*p+1], a0, a1, a2, a3, Bv[2], Bv[3]);
      }
    }
    __syncthreads();   // W, R, G(smem) all free now

    if (l < NL-1){
      // prefetch next layer weights/biases (overlaps writeback + flag wait)
      stage_weights(sbase, l+1, buf ^ 1, tid, conv_b, res_b);
      CP_COMMIT();

      // ---- writeback: xout = xin(A smem) + res + rb -> G smem + A first half ----
      const float* sRB = (const float*)(sm + buf*768 + 512);
      {
        char* aRow = sm + LOFF_A + (warp*16)*APITCH;
        char* gRow = sm + LOFF_G + (warp*16)*RPITCH;
        #pragma unroll
        for (int j = 0; j < 8; j++){
          int c0 = j*8 + q*2;
          float rb0 = sRB[c0], rb1 = sRB[c0+1];
          #pragma unroll
          for (int r = 0; r < 2; r++){
            int row = l4 + 8*r;
            uint32_t xp = *(const uint32_t*)(aRow + row*APITCH + j*16 + q*4);
            __nv_bfloat162 xb = *(__nv_bfloat162*)&xp;
            float o0 = __bfloat162float(xb.x) + r2[j][2*r]   + rb0;
            float o1 = __bfloat162float(xb.y) + r2[j][2*r+1] + rb1;
            uint32_t pk = pack2(o0, o1);
            *(uint32_t*)(gRow + row*RPITCH + j*16 + q*4) = pk;
            *(uint32_t*)(aRow + row*APITCH + j*16 + q*4) = pk;
          }
        }
      }
      __syncthreads();
      // coalesced xout -> global history buffer (l+1)
      __nv_bfloat16* xo = g_xh + (size_t)(l+1)*NTOK*NC + (size_t)tok0*NC;
      {
        #pragma unroll
        for (int i = 0; i < 4; i++){
          int idx = tid + i*256, row = idx >> 3, c = idx & 7;
          *(uint4*)((char*)xo + row*128 + c*16) = *(uint4*)(sm + LOFF_G + row*RPITCH + c*16);
        }
      }
      __syncthreads();
      // publish, then wait for neighbors
      if (tid == 0) red_rel(g_flags + cta);
      {
        int nb = cta - 1 - tid;
        if (tid < 4 && nb >= 0){
          while (ld_acq(g_flags + nb) < l + 1) __nanosleep(64);
        }
      }
      __syncthreads();
      // stage shifted half for layer l+1
      int dnext = 1 << ((l+1) % 10);
      stage_ashift(sbase, g_xh + (size_t)(l+1)*NTOK*NC, dnext, tok0, tid);
      CP_COMMIT();
    }
  }
}

// ---------------- head kernel ------------------------------------------------------
#define HOFF_SKB 0
#define HOFF_B0  1024
#define HOFF_B1  2048
#define HOFF_G0  3072
#define HOFF_WC0 21504
#define HOFF_G1  58368
#define HOFF_WC1 76800
#define HOFF_W2  3072
#define HSMEM    113664
#define WPITCH2  272

__device__ __forceinline__ void head_stage1(uint32_t sbase, int gOff, int wOff,
                                            int l, int tok0, int tid){
  const char* gs = (const char*)(g_gates + ((size_t)l*NTOK + tok0)*64);
  #pragma unroll
  for (int i = 0; i < 4; i++){
    int idx = tid + i*256, row = idx >> 3, c = idx & 7;
    cp16(sbase + gOff + row*RPITCH + c*16, gs + row*128 + c*16);
  }
  const char* ws = (const char*)(g_skipw + (size_t)l*16384);
  #pragma unroll
  for (int i = 0; i < 8; i++){
    int idx = tid + i*256, row = idx >> 3, c = idx & 7;
    cp16(sbase + wOff + row*RPITCH + c*16, ws + row*128 + c*16);
  }
  CP_COMMIT();
}

__global__ __launch_bounds__(256, 1) void head_kernel(
    const float* __restrict__ b0, const float* __restrict__ b1,
    const int* __restrict__ wf, const int* __restrict__ lens)
{
  extern __shared__ char sm[];
  uint32_t sbase = s2u(sm);
  const int tid = threadIdx.x, warp = tid >> 5, lane = tid & 31;
  const int l4 = lane >> 2, q = lane & 3;
  const int tok0 = blockIdx.x * 128;

  float* sSKB = (float*)(sm + HOFF_SKB);
  float* sB0  = (float*)(sm + HOFF_B0);
  float* sB1  = (float*)(sm + HOFF_B1);
  sSKB[tid] = g_skipb[tid];
  sB0[tid]  = b0[tid];
  sB1[tid]  = b1[tid];

  head_stage1(sbase, HOFF_G0, HOFF_WC0, 0, tok0, tid);
  head_stage1(sbase, HOFF_G1, HOFF_WC1, 1, tok0, tid);

  float acc[32][4];
  #pragma unroll
  for (int j = 0; j < 32; j++){ acc[j][0]=0; acc[j][1]=0; acc[j][2]=0; acc[j][3]=0; }

  const uint32_t aLane = (warp*16 + (lane & 15))*RPITCH + ((lane >> 4) << 4);
  const uint32_t bLane = ((lane & 7) + ((lane >> 4) << 3))*RPITCH + (((lane >> 3) & 1) << 4);

  for (int l = 0; l < NL; l++){
    int buf = l & 1;
    if (l < NL-1) CP_WAIT1(); else CP_WAIT0();
    __syncthreads();

    uint32_t aAddr = sbase + (buf ? HOFF_G1  : HOFF_G0)  + aLane;
    uint32_t bAddr = sbase + (buf ? HOFF_WC1 : HOFF_WC0) + bLane;
    #pragma unroll
    for (int s = 0; s < 4; s++){
      uint32_t A[4];
      ldsm4(A, aAddr + s*32);
      #pragma unroll
      for (int p = 0; p < 16; p++){
        uint32_t Bv[4];
        ldsm4(Bv, bAddr + p*16*RPITCH + s*32);
        mma16816(acc[2*p],   A[0], A[1], A[2], A[3], Bv[0], Bv[1]);
        mma16816(acc[2*p+1], A[0], A[1], A[2], A[3], Bv[2], Bv[3]);
      }
    }
    __syncthreads();
    if (l + 2 < NL)
      head_stage1(sbase, buf ? HOFF_G1 : HOFF_G0, buf ? HOFF_WC1 : HOFF_WC0,
                  l + 2, tok0, tid);
  }

  uint32_t P[32][2];
  #pragma unroll
  for (int j = 0; j < 32; j++){
    int c0 = j*8 + q*2;
    float s0 = sSKB[c0], s1 = sSKB[c0+1];
    P[j][0] = pack2(acc[j][0] + s0, acc[j][1] + s1);
    P[j][1] = pack2(acc[j][2] + s0, acc[j][3] + s1);
  }
  __syncthreads();

  const uint32_t bLane2 = ((lane & 7) + ((lane >> 4) << 3))*WPITCH2 + (((lane >> 3) & 1) << 4);

  // ---- phase 2: hid = relu(s @ w0^T + b0) ----
  #pragma unroll
  for (int j = 0; j < 32; j++){ acc[j][0]=0; acc[j][1]=0; acc[j][2]=0; acc[j][3]=0; }
  for (int kc = 0; kc < 2; kc++){
    {
      const char* ws = (const char*)g_w0t;
      #pragma unroll
      for (int i = 0; i < 16; i++){
        int idx = tid + i*256, row = idx >> 4, c = idx & 15;
        cp16(sbase + HOFF_W2 + row*WPITCH2 + c*16, ws + row*512 + kc*256 + c*16);
      }
      CP_COMMIT(); CP_WAIT0();
    }
    __syncthreads();
    #pragma unroll
    for (int s = 0; s < 8; s++){
      int S = kc*8 + s;
      uint32_t a0 = P[2*S][0], a1 = P[2*S][1], a2 = P[2*S+1][0], a3 = P[2*S+1][1];
      #pragma unroll
      for (int p = 0; p < 16; p++){
        uint32_t Bv[4];
        ldsm4(Bv, sbase + HOFF_W2 + bLane2 + p*16*WPITCH2 + s*32);
        mma16816(acc[2*p],   a0, a1, a2, a3, Bv[0], Bv[1]);
        mma16816(acc[2*p+1], a0, a1, a2, a3, Bv[2], Bv[3]);
      }
    }
    __syncthreads();
  }
  #pragma unroll
  for (int j = 0; j < 32; j++){
    int c0 = j*8 + q*2;
    float s0 = sB0[c0], s1 = sB0[c0+1];
    P[j][0] = pack2(fmaxf(acc[j][0] + s0, 0.f), fmaxf(acc[j][1] + s1, 0.f));
    P[j][1] = pack2(fmaxf(acc[j][2] + s0, 0.f), fmaxf(acc[j][3] + s1, 0.f));
  }

  // ---- phase 3: logits = hid @ w1^T ----
  #pragma unroll
  for (int j = 0; j < 32; j++){ acc[j][0]=0; acc[j][1]=0; acc[j][2]=0; acc[j][3]=0; }
  for (int kc = 0; kc < 2; kc++){
    {
      const char* ws = (const char*)g_w1t;
      #pragma unroll
      for (int i = 0; i < 16; i++){
        int idx = tid + i*256, row = idx >> 4, c = idx & 15;
        cp16(sbase + HOFF_W2 + row*WPITCH2 + c*16, ws + row*512 + kc*256 + c*16);
      }
      CP_COMMIT(); CP_WAIT0();
    }
    __syncthreads();
    #pragma unroll
    for (int s = 0; s < 8; s++){
      int S = kc*8 + s;
      uint32_t a0 = P[2*S][0], a1 = P[2*S][1], a2 = P[2*S+1][0], a3 = P[2*S+1][1];
      #pragma unroll
      for (int p = 0; p < 16; p++){
        uint32_t Bv[4];
        ldsm4(Bv, sbase + HOFF_W2 + bLane2 + p*16*WPITCH2 + s*32);
        mma16816(acc[2*p],   a0, a1, a2, a3, Bv[0], Bv[1]);
        mma16816(acc[2*p+1], a0, a1, a2, a3, Bv[2], Bv[3]);
      }
    }
    __syncthreads();
  }

  // ---- CE ----
  float local = 0.f;
  int tokA = tok0 + warp*16 + l4;
  #pragma unroll
  for (int r = 0; r < 2; r++){
    int tok = tokA + r*8;
    int lab = wf[tok];
    float m = -1e30f;
    #pragma unroll
    for (int j = 0; j < 32; j++){
      int c0 = j*8 + q*2;
      float v0 = acc[j][2*r]   + sB1[c0];
      float v1 = acc[j][2*r+1] + sB1[c0+1];
      m = fmaxf(m, fmaxf(v0, v1));
    }
    m = fmaxf(m, __shfl_xor_sync(0xffffffffu, m, 1));
    m = fmaxf(m, __shfl_xor_sync(0xffffffffu, m, 2));
    float s = 0.f, lv = 0.f;
    #pragma unroll
    for (int j = 0; j < 32; j++){
      int c0 = j*8 + q*2;
      float v0 = acc[j][2*r]   + sB1[c0];
      float v1 = acc[j][2*r+1] + sB1[c0+1];
      s += __expf(v0 - m) + __expf(v1 - m);
      if (lab == c0)   lv += v0;
      if (lab == c0+1) lv += v1;
    }
    s  += __shfl_xor_sync(0xffffffffu, s, 1);
    s  += __shfl_xor_sync(0xffffffffu, s, 2);
    lv += __shfl_xor_sync(0xffffffffu, lv, 1);
    lv += __shfl_xor_sync(0xffffffffu, lv, 2);
    float ce = m + logf(s) - lv;
    int t = tok & (NT-1);
    int b = tok >> 13;
    if (q == 0 && t < lens[b]) local += ce;
  }
  #pragma unroll
  for (int off = 16; off; off >>= 1)
    local += __shfl_xor_sync(0xffffffffu, local, off);
  if (lane == 0) atomicAdd(&g_num, local);
}

__global__ void finalize_kernel(const int* __restrict__ lens, float* __restrict__ out){
  float denom = 0.f;
  for (int b = 0; b < NB; b++) denom += (float)lens[b];
  out[0] = g_num / fmaxf(denom, 1.f);
}

// ---------------- launcher ----------------------------------------------------------
extern "C" void kernel_launch(void* const* d_in, const int* in_sizes, int n_in,
                              void* d_out, int out_size)
{
  const int*   wf     = (const int*)d_in[0];
  const int*   lens   = (const int*)d_in[1];
  const float* emb    = (const float*)d_in[2];
  const float* conv_w = (const float*)d_in[3];
  const float* conv_b = (const float*)d_in[4];
  const float* res_w  = (const float*)d_in[5];
  const float* res_b  = (const float*)d_in[6];
  const float* skip_w = (const float*)d_in[7];
  const float* skip_b = (const float*)d_in[8];
  const float* w0     = (const float*)d_in[9];
  const float* b0     = (const float*)d_in[10];
  const float* w1     = (const float*)d_in[11];
  const float* b1     = (const float*)d_in[12];

  cudaFuncSetAttribute(layers_kernel, cudaFuncAttributeMaxDynamicSharedMemorySize, LSMEM);
  cudaFuncSetAttribute(head_kernel,   cudaFuncAttributeMaxDynamicSharedMemorySize, HSMEM);

  prep_misc_kernel<<<1, NS>>>(skip_b);
  prep_w_kernel<<<4832, 256>>>(conv_w, res_w, skip_w, w0, w1);
  embed_kernel<<<NTOK/4, 256>>>(wf, emb);
  layers_kernel<<<NTOK/128, 256, LSMEM>>>(conv_b, res_b);
  head_kernel<<<NTOK/128, 256, HSMEM>>>(b0, b1, wf, lens);
  finalize_kernel<<<1, 1>>>(lens, (float*)d_out);
}

// round 8
// speedup vs baseline: 12.4105x; 1.0171x over previous
#include <cuda_runtime.h>
#include <cuda_bf16.h>
#include <math.h>
#include <stdint.h>

#define NB 4
#define NT 8192
#define NC 64
#define NS 256
#define NV 256
#define NL 30
#define NTOK (NB*NT)

// ---------------- device scratch ---------------------------------------------
__device__ __nv_bfloat16 g_xh[(size_t)(NL+1)*NTOK*NC];  // per-layer x history
__device__ __nv_bfloat16 g_gates[(size_t)NL*NTOK*NC];   // [l][tok][64]
__device__ __nv_bfloat16 g_convw[NL*128*128];           // [l][f][k]
__device__ __nv_bfloat16 g_resw[NL*64*64];              // [l][o][k]
__device__ __nv_bfloat16 g_skipw[NL*256*64];            // [l][v][k]
__device__ __nv_bfloat16 g_w0t[256*256];                // [v][k]
__device__ __nv_bfloat16 g_w1t[256*256];                // [v][k]
__device__ float g_skipb[NS];
__device__ float g_num;
__device__ int   g_flags[256];

// ---------------- helpers ------------------------------------------------------
__device__ __forceinline__ uint32_t s2u(const void* p){
  uint32_t a;
  asm("{ .reg .u64 t; cvta.to.shared.u64 t, %1; cvt.u32.u64 %0, t; }" : "=r"(a) : "l"(p));
  return a;
}
__device__ __forceinline__ void mma16816(float* c, uint32_t a0, uint32_t a1,
                                         uint32_t a2, uint32_t a3,
                                         uint32_t b0, uint32_t b1){
  asm volatile("mma.sync.aligned.m16n8k16.row.col.f32.bf16.bf16.f32 "
    "{%0,%1,%2,%3}, {%4,%5,%6,%7}, {%8,%9}, {%0,%1,%2,%3};"
    : "+f"(c[0]), "+f"(c[1]), "+f"(c[2]), "+f"(c[3])
    : "r"(a0), "r"(a1), "r"(a2), "r"(a3), "r"(b0), "r"(b1));
}
__device__ __forceinline__ void ldsm4(uint32_t* r, uint32_t a){
  asm volatile("ldmatrix.sync.aligned.m8n8.x4.shared.b16 {%0,%1,%2,%3}, [%4];"
    : "=r"(r[0]), "=r"(r[1]), "=r"(r[2]), "=r"(r[3]) : "r"(a));
}
__device__ __forceinline__ void cp16(uint32_t d, const void* s){
  asm volatile("cp.async.ca.shared.global [%0], [%1], 16;" :: "r"(d), "l"(s));
}
__device__ __forceinline__ void cp16g(uint32_t d, const void* s){
  asm volatile("cp.async.cg.shared.global [%0], [%1], 16;" :: "r"(d), "l"(s));
}
__device__ __forceinline__ void cp16zg(uint32_t d, const void* s, int pred){
  asm volatile("{\n .reg .pred p;\n setp.ne.b32 p, %2, 0;\n"
    " @p  cp.async.cg.shared.global [%0], [%1], 16;\n"
    " @!p cp.async.cg.shared.global [%0], [%1], 16, 0;\n}"
    :: "r"(d), "l"(s), "r"(pred));
}
#define CP_COMMIT() asm volatile("cp.async.commit_group;" ::: "memory")
#define CP_WAIT0()  asm volatile("cp.async.wait_group 0;" ::: "memory")
#define CP_WAIT1()  asm volatile("cp.async.wait_group 1;" ::: "memory")

__device__ __forceinline__ uint32_t pack2(float a, float b){
  __nv_bfloat162 t = __floats2bfloat162_rn(a, b);
  return *(uint32_t*)&t;
}
__device__ __forceinline__ float tanh_ap(float x){
  float r;
  asm("tanh.approx.f32 %0, %1;" : "=f"(r) : "f"(x));
  return r;
}
__device__ __forceinline__ int ld_acq(const int* p){
  int v;
  asm volatile("ld.acquire.gpu.global.b32 %0, [%1];" : "=r"(v) : "l"(p) : "memory");
  return v;
}
__device__ __forceinline__ void red_rel(int* p){
  asm volatile("red.release.gpu.global.add.s32 [%0], %1;" :: "l"(p), "r"(1) : "memory");
}

// ---------------- prep ----------------------------------------------------------
__global__ void prep_w_kernel(const float* __restrict__ conv_w,
                              const float* __restrict__ res_w,
                              const float* __restrict__ skip_w,
                              const float* __restrict__ w0,
                              const float* __restrict__ w1){
  int idx = blockIdx.x*256 + threadIdx.x;
  if (idx < NL*128*128){
    int k = idx & 127, f = (idx>>7)&127, l = idx>>14;
    float v = (k < 64) ? conv_w[((l*2+1)*64 + k)*128 + f]
                       : conv_w[((l*2+0)*64 + (k-64))*128 + f];
    g_convw[((size_t)l*128 + f)*128 + k] = __float2bfloat16(v);
    return;
  }
  idx -= NL*128*128;
  if (idx < NL*64*64){
    int k = idx & 63, o = (idx>>6)&63, l = idx>>12;
    g_resw[((size_t)l*64 + o)*64 + k] = __float2bfloat16(res_w[((size_t)l*64 + k)*64 + o]);
    return;
  }
  idx -= NL*64*64;
  if (idx < NL*256*64){
    int k = idx & 63, v2 = (idx>>6)&255, l = idx>>14;
    g_skipw[((size_t)l*256 + v2)*64 + k] = __float2bfloat16(skip_w[((size_t)l*64 + k)*256 + v2]);
    return;
  }
  idx -= NL*256*64;
  if (idx < 256*256){
    int k = idx & 255, v2 = idx>>8;
    g_w0t[v2*256 + k] = __float2bfloat16(w0[k*256 + v2]);
    return;
  }
  idx -= 256*256;
  if (idx < 256*256){
    int k = idx & 255, v2 = idx>>8;
    g_w1t[v2*256 + k] = __float2bfloat16(w1[k*256 + v2]);
  }
}

__global__ void prep_misc_kernel(const float* __restrict__ skip_b){
  int s = threadIdx.x;
  float a = 0.f;
  #pragma unroll 6
  for (int l = 0; l < NL; l++) a += skip_b[l*NS + s];
  g_skipb[s] = a;
  g_flags[s] = 0;
  if (s == 0) g_num = 0.f;
}

__global__ void embed_kernel(const int* __restrict__ wf, const float* __restrict__ emb){
  int tid = threadIdx.x;
  int tok = blockIdx.x*4 + (tid >> 6);
  int c   = tid & 63;
  int t   = tok & (NT-1);
  int lab = (t == 0) ? 128 : wf[tok-1];
  g_xh[(size_t)tok*NC + c] = __float2bfloat16(emb[lab*NC + c]);
}

// ---------------- fused 30-layer kernel -----------------------------------------
#define LOFF_A  1536
#define LOFF_W  36352
#define LOFF_R  71168
#define LOFF_G  80384
#define LSMEM   98816
#define APITCH  272
#define RPITCH  144

__device__ __forceinline__ void stage_weights(uint32_t sbase, int l, int buf, int tid,
                                              const float* conv_b, const float* res_b){
  if (tid < 32) cp16(sbase + buf*768 + tid*16, (const char*)(conv_b + l*128) + tid*16);
  else if (tid < 48) cp16(sbase + buf*768 + 512 + (tid-32)*16,
                          (const char*)(res_b + l*64) + (tid-32)*16);
  const char* wsrc = (const char*)(g_convw + (size_t)l*16384);
  #pragma unroll
  for (int i = 0; i < 8; i++){
    int idx = tid + i*256, row = idx >> 4, c = idx & 15;
    cp16(sbase + LOFF_W + row*APITCH + c*16, wsrc + row*256 + c*16);
  }
  const char* rsrc = (const char*)(g_resw + (size_t)l*4096);
  #pragma unroll
  for (int i = 0; i < 2; i++){
    int idx = tid + i*256, row = idx >> 3, c = idx & 7;
    cp16(sbase + LOFF_R + row*RPITCH + c*16, rsrc + row*128 + c*16);
  }
}

// phase 0: rows whose source is our own tokens (row >= d) or zero-fill (t < d)
// phase 1: rows needing a neighbor CTA's xh (row < d && t >= d)
__device__ __forceinline__ void stage_ashift_part(uint32_t sbase, const __nv_bfloat16* xsrc,
                                                  int dL, int tok0, int tid, int phase){
  #pragma unroll
  for (int i = 0; i < 4; i++){
    int idx = tid + i*256;
    int row = idx >> 3, c = idx & 7;
    int tok = tok0 + row, t = tok & (NT-1);
    int own = (row >= dL) || (t < dL);
    if ((phase == 0) == (own != 0))
      cp16zg(sbase + LOFF_A + row*APITCH + 128 + c*16,
             (const char*)(xsrc + (long)(tok - dL)*64) + c*16, t >= dL);
  }
}

__global__ __launch_bounds__(256, 2) void layers_kernel(
    const float* __restrict__ conv_b, const float* __restrict__ res_b)
{
  extern __shared__ char sm[];
  uint32_t sbase = s2u(sm);
  const int tid = threadIdx.x, warp = tid >> 5, lane = tid & 31;
  const int l4 = lane >> 2, q = lane & 3;
  const int cta = blockIdx.x;
  const int tok0 = cta * 128;

  // ---- prologue: layer-0 weights + full A tile ----
  stage_weights(sbase, 0, 0, tid, conv_b, res_b);
  {
    const char* xs = (const char*)(g_xh + (size_t)tok0*64);
    #pragma unroll
    for (int i = 0; i < 4; i++){
      int idx = tid + i*256, row = idx >> 3, c = idx & 7;
      cp16g(sbase + LOFF_A + row*APITCH + c*16, xs + row*128 + c*16);
    }
    #pragma unroll
    for (int i = 0; i < 4; i++){
      int idx = tid + i*256, row = idx >> 3, c = idx & 7;
      int tok = tok0 + row, t = tok & (NT-1);
      cp16zg(sbase + LOFF_A + row*APITCH + 128 + c*16,
             (const char*)(g_xh + (long)(tok - 1)*64) + c*16, t >= 1);
    }
  }
  CP_COMMIT();

  const uint32_t aAddr = sbase + LOFF_A + (warp*16 + (lane & 15))*APITCH + ((lane >> 4) << 4);
  const uint32_t bAddr = sbase + LOFF_W + ((lane & 7) + ((lane >> 4) << 3))*APITCH
                       + (((lane >> 3) & 1) << 4);
  const uint32_t rAddr = sbase + LOFF_R + ((lane & 7) + ((lane >> 4) << 3))*RPITCH
                       + (((lane >> 3) & 1) << 4);

  for (int l = 0; l < NL; l++){
    const int buf = l & 1;
    CP_WAIT0();
    __syncthreads();   // A(half2)+weights+biases ready

    // ---- conv GEMM: 16 tok x 128 N per warp, K=128 ----
    float acc[16][4];
    #pragma unroll
    for (int j = 0; j < 16; j++){ acc[j][0]=0; acc[j][1]=0; acc[j][2]=0; acc[j][3]=0; }
    #pragma unroll
    for (int s = 0; s < 8; s++){
      uint32_t A[4];
      ldsm4(A, aAddr + s*32);
      #pragma unroll
      for (int p = 0; p < 8; p++){
        uint32_t Bv[4];
        ldsm4(Bv, bAddr + p*16*APITCH + s*32);
        mma16816(acc[2*p],   A[0], A[1], A[2], A[3], Bv[0], Bv[1]);
        mma16816(acc[2*p+1], A[0], A[1], A[2], A[3], Bv[2], Bv[3]);
      }
    }

    // ---- gate ----
    const float* sCB = (const float*)(sm + buf*768);
    uint32_t G[8][2];
    #pragma unroll
    for (int j = 0; j < 8; j++){
      int c0 = j*8 + q*2;
      float b1c = sCB[c0], b2c = sCB[c0+1], b1s = sCB[64+c0], b2s = sCB[64+c0+1];
      #pragma unroll
      for (int r = 0; r < 2; r++){
        float h1a = acc[j][2*r]     + b1c;
        float h1b = acc[j][2*r+1]   + b2c;
        float h2a = acc[j+8][2*r]   + b1s;
        float h2b = acc[j+8][2*r+1] + b2s;
        float ga = tanh_ap(h1a) * fmaf(0.5f, tanh_ap(0.5f*h2a), 0.5f);
        float gb = tanh_ap(h1b) * fmaf(0.5f, tanh_ap(0.5f*h2b), 0.5f);
        G[j][r] = pack2(ga, gb);
      }
    }

    // ---- residual GEMM (A-frags = gate regs) ----
    float r2[8][4];
    #pragma unroll
    for (int j = 0; j < 8; j++){ r2[j][0]=0; r2[j][1]=0; r2[j][2]=0; r2[j][3]=0; }
    #pragma unroll
    for (int s = 0; s < 4; s++){
      uint32_t a0 = G[2*s][0], a1 = G[2*s][1], a2 = G[2*s+1][0], a3 = G[2*s+1][1];
      #pragma unroll
      for (int p = 0; p < 4; p++){
        uint32_t Bv[4];
        ldsm4(Bv, rAddr + p*16*RPITCH + s*32);
        mma16816(r2[2*p],   a0, a1, a2, a3, Bv[0], Bv[1]);
        mma16816(r2[2*p+1], a0, a1, a2, a3, Bv[2], Bv[3]);
      }
    }

    // ---- writeback in-place into A half1 (warp-private rows) + gate STS ----
    {
      const float* sRB = (const float*)(sm + buf*768 + 512);
      char* aRow = sm + LOFF_A + (warp*16)*APITCH;
      char* gRow = sm + LOFF_G + (warp*16)*RPITCH;
      #pragma unroll
      for (int j = 0; j < 8; j++){
        int c0 = j*8 + q*2;
        float rb0 = sRB[c0], rb1 = sRB[c0+1];
        #pragma unroll
        for (int r = 0; r < 2; r++){
          int row = l4 + 8*r;
          uint32_t xp = *(const uint32_t*)(aRow + row*APITCH + j*16 + q*4);
          __nv_bfloat162 xb = *(__nv_bfloat162*)&xp;
          float o0 = __bfloat162float(xb.x) + r2[j][2*r]   + rb0;
          float o1 = __bfloat162float(xb.y) + r2[j][2*r+1] + rb1;
          *(uint32_t*)(aRow + row*APITCH + j*16 + q*4) = pack2(o0, o1);
          *(uint32_t*)(gRow + row*RPITCH + j*16 + q*4) = G[j][r];
        }
      }
    }
    __syncthreads();   // STS visible; all MMA reads of A/W/R/G complete

    // ---- global stores (gates always; xh when another layer follows) ----
    {
      char* gd = (char*)(g_gates + ((size_t)l*NTOK + tok0)*64);
      #pragma unroll
      for (int i = 0; i < 4; i++){
        int idx = tid + i*256, row = idx >> 3, c = idx & 7;
        *(uint4*)(gd + row*128 + c*16) = *(uint4*)(sm + LOFF_G + row*RPITCH + c*16);
      }
    }
    if (l < NL-1){
      char* xo = (char*)(g_xh + (size_t)(l+1)*NTOK*NC + (size_t)tok0*NC);
      #pragma unroll
      for (int i = 0; i < 4; i++){
        int idx = tid + i*256, row = idx >> 3, c = idx & 7;
        *(uint4*)(xo + row*128 + c*16) = *(uint4*)(sm + LOFF_A + row*APITCH + c*16);
      }
      stage_weights(sbase, l+1, buf ^ 1, tid, conv_b, res_b);   // cp.async (starts now)
      __syncthreads();   // xh STG visible CTA-wide + ordered before flag release

      const int dnext = 1 << ((l+1) % 10);
      const __nv_bfloat16* xsrc = g_xh + (size_t)(l+1)*NTOK*NC;
      stage_ashift_part(sbase, xsrc, dnext, tok0, tid, 0);      // own/zero rows now
      if (tid == 0){
        red_rel(g_flags + cta);
        int step = dnext >> 7; if (step == 0) step = 1;
        int nb = cta - step;
        if (nb >= 0){
          while (ld_acq(g_flags + nb) < l + 1) __nanosleep(32);
        }
      }
      __syncthreads();   // neighbor xh ready
      stage_ashift_part(sbase, xsrc, dnext, tok0, tid, 1);      // neighbor rows
      CP_COMMIT();
    }
  }
}

// ---------------- head kernel ------------------------------------------------------
#define HOFF_SKB 0
#define HOFF_B0  1024
#define HOFF_B1  2048
#define HOFF_G0  3072
#define HOFF_WC0 21504
#define HOFF_G1  58368
#define HOFF_WC1 76800
#define HOFF_W2  3072
#define HSMEM    113664
#define WPITCH2  272

__device__ __forceinline__ void head_stage1(uint32_t sbase, int gOff, int wOff,
                                            int l, int tok0, int tid){
  const char* gs = (const char*)(g_gates + ((size_t)l*NTOK + tok0)*64);
  #pragma unroll
  for (int i = 0; i < 4; i++){
    int idx = tid + i*256, row = idx >> 3, c = idx & 7;
    cp16(sbase + gOff + row*RPITCH + c*16, gs + row*128 + c*16);
  }
  const char* ws = (const char*)(g_skipw + (size_t)l*16384);
  #pragma unroll
  for (int i = 0; i < 8; i++){
    int idx = tid + i*256, row = idx >> 3, c = idx & 7;
    cp16(sbase + wOff + row*RPITCH + c*16, ws + row*128 + c*16);
  }
  CP_COMMIT();
}

__global__ __launch_bounds__(256, 1) void head_kernel(
    const float* __restrict__ b0, const float* __restrict__ b1,
    const int* __restrict__ wf, const int* __restrict__ lens)
{
  extern __shared__ char sm[];
  uint32_t sbase = s2u(sm);
  const int tid = threadIdx.x, warp = tid >> 5, lane = tid & 31;
  const int l4 = lane >> 2, q = lane & 3;
  const int tok0 = blockIdx.x * 128;

  float* sSKB = (float*)(sm + HOFF_SKB);
  float* sB0  = (float*)(sm + HOFF_B0);
  float* sB1  = (float*)(sm + HOFF_B1);
  sSKB[tid] = g_skipb[tid];
  sB0[tid]  = b0[tid];
  sB1[tid]  = b1[tid];

  head_stage1(sbase, HOFF_G0, HOFF_WC0, 0, tok0, tid);
  head_stage1(sbase, HOFF_G1, HOFF_WC1, 1, tok0, tid);

  float acc[32][4];
  #pragma unroll
  for (int j = 0; j < 32; j++){ acc[j][0]=0; acc[j][1]=0; acc[j][2]=0; acc[j][3]=0; }

  const uint32_t aLane = (warp*16 + (lane & 15))*RPITCH + ((lane >> 4) << 4);
  const uint32_t bLane = ((lane & 7) + ((lane >> 4) << 3))*RPITCH + (((lane >> 3) & 1) << 4);

  for (int l = 0; l < NL; l++){
    int buf = l & 1;
    if (l < NL-1) CP_WAIT1(); else CP_WAIT0();
    __syncthreads();

    uint32_t aAddr = sbase + (buf ? HOFF_G1  : HOFF_G0)  + aLane;
    uint32_t bAddr = sbase + (buf ? HOFF_WC1 : HOFF_WC0) + bLane;
    #pragma unroll
    for (int s = 0; s < 4; s++){
      uint32_t A[4];
      ldsm4(A, aAddr + s*32);
      #pragma unroll
      for (int p = 0; p < 16; p++){
        uint32_t Bv[4];
        ldsm4(Bv, bAddr + p*16*RPITCH + s*32);
        mma16816(acc[2*p],   A[0], A[1], A[2], A[3], Bv[0], Bv[1]);
        mma16816(acc[2*p+1], A[0], A[1], A[2], A[3], Bv[2], Bv[3]);
      }
    }
    __syncthreads();
    if (l + 2 < NL)
      head_stage1(sbase, buf ? HOFF_G1 : HOFF_G0, buf ? HOFF_WC1 : HOFF_WC0,
                  l + 2, tok0, tid);
  }

  uint32_t P[32][2];
  #pragma unroll
  for (int j = 0; j < 32; j++){
    int c0 = j*8 + q*2;
    float s0 = sSKB[c0], s1 = sSKB[c0+1];
    P[j][0] = pack2(acc[j][0] + s0, acc[j][1] + s1);
    P[j][1] = pack2(acc[j][2] + s0, acc[j][3] + s1);
  }
  __syncthreads();

  const uint32_t bLane2 = ((lane & 7) + ((lane >> 4) << 3))*WPITCH2 + (((lane >> 3) & 1) << 4);

  // ---- phase 2: hid = relu(s @ w0^T + b0) ----
  #pragma unroll
  for (int j = 0; j < 32; j++){ acc[j][0]=0; acc[j][1]=0; acc[j][2]=0; acc[j][3]=0; }
  for (int kc = 0; kc < 2; kc++){
    {
      const char* ws = (const char*)g_w0t;
      #pragma unroll
      for (int i = 0; i < 16; i++){
        int idx = tid + i*256, row = idx >> 4, c = idx & 15;
        cp16(sbase + HOFF_W2 + row*WPITCH2 + c*16, ws + row*512 + kc*256 + c*16);
      }
      CP_COMMIT(); CP_WAIT0();
    }
    __syncthreads();
    #pragma unroll
    for (int s = 0; s < 8; s++){
      int S = kc*8 + s;
      uint32_t a0 = P[2*S][0], a1 = P[2*S][1], a2 = P[2*S+1][0], a3 = P[2*S+1][1];
      #pragma unroll
      for (int p = 0; p < 16; p++){
        uint32_t Bv[4];
        ldsm4(Bv, sbase + HOFF_W2 + bLane2 + p*16*WPITCH2 + s*32);
        mma16816(acc[2*p],   a0, a1, a2, a3, Bv[0], Bv[1]);
        mma16816(acc[2*p+1], a0, a1, a2, a3, Bv[2], Bv[3]);
      }
    }
    __syncthreads();
  }
  #pragma unroll
  for (int j = 0; j < 32; j++){
    int c0 = j*8 + q*2;
    float s0 = sB0[c0], s1 = sB0[c0+1];
    P[j][0] = pack2(fmaxf(acc[j][0] + s0, 0.f), fmaxf(acc[j][1] + s1, 0.f));
    P[j][1] = pack2(fmaxf(acc[j][2] + s0, 0.f), fmaxf(acc[j][3] + s1, 0.f));
  }

  // ---- phase 3: logits = hid @ w1^T ----
  #pragma unroll
  for (int j = 0; j < 32; j++){ acc[j][0]=0; acc[j][1]=0; acc[j][2]=0; acc[j][3]=0; }
  for (int kc = 0; kc < 2; kc++){
    {
      const char* ws = (const char*)g_w1t;
      #pragma unroll
      for (int i = 0; i < 16; i++){
        int idx = tid + i*256, row = idx >> 4, c = idx & 15;
        cp16(sbase + HOFF_W2 + row*WPITCH2 + c*16, ws + row*512 + kc*256 + c*16);
      }
      CP_COMMIT(); CP_WAIT0();
    }
    __syncthreads();
    #pragma unroll
    for (int s = 0; s < 8; s++){
      int S = kc*8 + s;
      uint32_t a0 = P[2*S][0], a1 = P[2*S][1], a2 = P[2*S+1][0], a3 = P[2*S+1][1];
      #pragma unroll
      for (int p = 0; p < 16; p++){
        uint32_t Bv[4];
        ldsm4(Bv, sbase + HOFF_W2 + bLane2 + p*16*WPITCH2 + s*32);
        mma16816(acc[2*p],   a0, a1, a2, a3, Bv[0], Bv[1]);
        mma16816(acc[2*p+1], a0, a1, a2, a3, Bv[2], Bv[3]);
      }
    }
    __syncthreads();
  }

  // ---- CE ----
  float local = 0.f;
  int tokA = tok0 + warp*16 + l4;
  #pragma unroll
  for (int r = 0; r < 2; r++){
    int tok = tokA + r*8;
    int lab = wf[tok];
    float m = -1e30f;
    #pragma unroll
    for (int j = 0; j < 32; j++){
      int c0 = j*8 + q*2;
      float v0 = acc[j][2*r]   + sB1[c0];
      float v1 = acc[j][2*r+1] + sB1[c0+1];
      m = fmaxf(m, fmaxf(v0, v1));
    }
    m = fmaxf(m, __shfl_xor_sync(0xffffffffu, m, 1));
    m = fmaxf(m, __shfl_xor_sync(0xffffffffu, m, 2));
    float s = 0.f, lv = 0.f;
    #pragma unroll
    for (int j = 0; j < 32; j++){
      int c0 = j*8 + q*2;
      float v0 = acc[j][2*r]   + sB1[c0];
      float v1 = acc[j][2*r+1] + sB1[c0+1];
      s += __expf(v0 - m) + __expf(v1 - m);
      if (lab == c0)   lv += v0;
      if (lab == c0+1) lv += v1;
    }
    s  += __shfl_xor_sync(0xffffffffu, s, 1);
    s  += __shfl_xor_sync(0xffffffffu, s, 2);
    lv += __shfl_xor_sync(0xffffffffu, lv, 1);
    lv += __shfl_xor_sync(0xffffffffu, lv, 2);
    float ce = m + logf(s) - lv;
    int t = tok & (NT-1);
    int b = tok >> 13;
    if (q == 0 && t < lens[b]) local += ce;
  }
  #pragma unroll
  for (int off = 16; off; off >>= 1)
    local += __shfl_xor_sync(0xffffffffu, local, off);
  if (lane == 0) atomicAdd(&g_num, local);
}

__global__ void finalize_kernel(const int* __restrict__ lens, float* __restrict__ out){
  float denom = 0.f;
  for (int b = 0; b < NB; b++) denom += (float)lens[b];
  out[0] = g_num / fmaxf(denom, 1.f);
}

// ---------------- launcher ----------------------------------------------------------
extern "C" void kernel_launch(void* const* d_in, const int* in_sizes, int n_in,
                              void* d_out, int out_size)
{
  const int*   wf     = (const int*)d_in[0];
  const int*   lens   = (const int*)d_in[1];
  const float* emb    = (const float*)d_in[2];
  const float* conv_w = (const float*)d_in[3];
  const float* conv_b = (const float*)d_in[4];
  const float* res_w  = (const float*)d_in[5];
  const float* res_b  = (const float*)d_in[6];
  const float* skip_w = (const float*)d_in[7];
  const float* skip_b = (const float*)d_in[8];
  const float* w0     = (const float*)d_in[9];
  const float* b0     = (const float*)d_in[10];
  const float* w1     = (const float*)d_in[11];
  const float* b1     = (const float*)d_in[12];

  cudaFuncSetAttribute(layers_kernel, cudaFuncAttributeMaxDynamicSharedMemorySize, LSMEM);
  cudaFuncSetAttribute(head_kernel,   cudaFuncAttributeMaxDynamicSharedMemorySize, HSMEM);

  prep_misc_kernel<<<1, NS>>>(skip_b);
  prep_w_kernel<<<4832, 256>>>(conv_w, res_w, skip_w, w0, w1);
  embed_kernel<<<NTOK/4, 256>>>(wf, emb);
  layers_kernel<<<NTOK/128, 256, LSMEM>>>(conv_b, res_b);
  head_kernel<<<NTOK/128, 256, HSMEM>>>(b0, b1, wf, lens);
  finalize_kernel<<<1, 1>>>(lens, (float*)d_out);
}